// round 10
// baseline (speedup 1.0000x reference)
#include <cuda_runtime.h>
#include <cuda_bf16.h>
#include <cstdint>

#define LOG2E 1.4426950408889634f
#define NP  16384
#define NT  256      // j-tiles of 64
#define NWG 1024     // i row-groups of 16
#define NSL 9        // j-slices: 4x29 + 5x28 = 256

// ---- static device scratch (no allocation) ----
__device__ uint32_t g_Xf[NWG * 32 * 16];  // a-frag image
__device__ uint32_t g_Yf[NT * 2048];      // b-frag image (GEMM1)
__device__ uint32_t g_Bf[NT * 1024];      // b-frag image (GEMM2)
__device__ float g_cxn[NP];
__device__ float g_cyn[NP];
__device__ float g_Op[NSL * NP * 16];     // per-slice fp32 partials (9 MB)

// ---- helpers ----
__device__ __forceinline__ uint32_t smem_u32(const void* p) {
    uint32_t a;
    asm("{ .reg .u64 t; cvta.to.shared.u64 t, %1; cvt.u32.u64 %0, t; }" : "=r"(a) : "l"(p));
    return a;
}
__device__ __forceinline__ void cp16(uint32_t d, const void* s) {
    asm volatile("cp.async.cg.shared.global [%0], [%1], 16;" :: "r"(d), "l"(s));
}
#define CP_COMMIT() asm volatile("cp.async.commit_group;" ::: "memory")
#define CP_WAIT0()  asm volatile("cp.async.wait_group 0;" ::: "memory")

__device__ __forceinline__ void mma_bf16(float* d, const uint32_t* a, uint32_t b0, uint32_t b1) {
    asm volatile("mma.sync.aligned.m16n8k16.row.col.f32.bf16.bf16.f32 "
                 "{%0,%1,%2,%3},{%4,%5,%6,%7},{%8,%9},{%0,%1,%2,%3};"
                 : "+f"(d[0]), "+f"(d[1]), "+f"(d[2]), "+f"(d[3])
                 : "r"(a[0]), "r"(a[1]), "r"(a[2]), "r"(a[3]), "r"(b0), "r"(b1));
}
__device__ __forceinline__ float ex2f(float a) {
    float r; asm("ex2.approx.ftz.f32 %0, %1;" : "=f"(r) : "f"(a)); return r;
}
__device__ __forceinline__ uint32_t pk2(float lo, float hi) {
    __nv_bfloat162 h = __float22bfloat162_rn(make_float2(lo, hi));
    return *(uint32_t*)&h;
}
__device__ __forceinline__ float bflo(uint32_t u) { return __uint_as_float(u << 16); }
__device__ __forceinline__ float bfhi(uint32_t u) { return __uint_as_float(u & 0xffff0000u); }
__device__ __forceinline__ uint32_t pk_split(float a, float b, int low) {
    float ah = __bfloat162float(__float2bfloat16(a));
    float bh = __bfloat162float(__float2bfloat16(b));
    return low ? pk2(a - ah, b - bh) : pk2(ah, bh);
}

// ================= prep kernels (unchanged) =================
__global__ void prep_x(const float* __restrict__ ls, const float* __restrict__ x) {
    int t = blockIdx.x * 128 + threadIdx.x;
    int wg = t >> 5, l = t & 31;
    int r0 = wg * 16 + (l >> 2), r1 = r0 + 8;
    int c = 2 * (l & 3);
    const float* x0 = x + (size_t)r0 * 32;
    const float* x1 = x + (size_t)r1 * 32;
    float v0[8], v1[8], n0 = 0.f, n1 = 0.f;
#pragma unroll
    for (int kf = 0; kf < 2; kf++)
#pragma unroll
        for (int h = 0; h < 2; h++)
#pragma unroll
            for (int e = 0; e < 2; e++) {
                int idx = kf * 4 + h * 2 + e;
                int col = kf * 16 + h * 8 + c + e;
                v0[idx] = x0[col]; v1[idx] = x1[col];
                n0 += v0[idx] * v0[idx];
                n1 += v1[idx] * v1[idx];
            }
    n0 += __shfl_xor_sync(0xffffffffu, n0, 1); n0 += __shfl_xor_sync(0xffffffffu, n0, 2);
    n1 += __shfl_xor_sync(0xffffffffu, n1, 1); n1 += __shfl_xor_sync(0xffffffffu, n1, 2);
    const float cneg = -ls[0] * LOG2E;
    if ((l & 3) == 0) { g_cxn[r0] = cneg * n0; g_cxn[r1] = cneg * n1; }

    uint32_t o[16];
#pragma unroll
    for (int s = 0; s < 2; s++)
#pragma unroll
        for (int kf = 0; kf < 2; kf++)
#pragma unroll
            for (int h = 0; h < 2; h++) {
                o[s * 8 + kf * 4 + h * 2 + 0] = pk_split(v0[kf * 4 + h * 2], v0[kf * 4 + h * 2 + 1], s);
                o[s * 8 + kf * 4 + h * 2 + 1] = pk_split(v1[kf * 4 + h * 2], v1[kf * 4 + h * 2 + 1], s);
            }
    uint4* dst = (uint4*)(g_Xf + (size_t)t * 16);
#pragma unroll
    for (int q = 0; q < 4; q++) dst[q] = make_uint4(o[4 * q], o[4 * q + 1], o[4 * q + 2], o[4 * q + 3]);
}

__global__ void prep_y(const float* __restrict__ ls, const float* __restrict__ y) {
    int t = blockIdx.x * 128 + threadIdx.x;
    int tn = t >> 5, l = t & 31;
    int j = tn * 8 + (l >> 2);
    int c = 2 * (l & 3);
    const float* yr = y + (size_t)j * 32;
    float v[8], n = 0.f;
#pragma unroll
    for (int kf = 0; kf < 2; kf++)
#pragma unroll
        for (int h = 0; h < 2; h++)
#pragma unroll
            for (int e = 0; e < 2; e++) {
                int idx = kf * 4 + h * 2 + e;
                v[idx] = yr[kf * 16 + h * 8 + c + e];
                n += v[idx] * v[idx];
            }
    n += __shfl_xor_sync(0xffffffffu, n, 1); n += __shfl_xor_sync(0xffffffffu, n, 2);
    if ((l & 3) == 0) g_cyn[j] = -ls[0] * LOG2E * n;

    uint32_t o[8];
#pragma unroll
    for (int s = 0; s < 2; s++)
#pragma unroll
        for (int kf = 0; kf < 2; kf++)
#pragma unroll
            for (int h = 0; h < 2; h++)
                o[s * 4 + kf * 2 + h] = pk_split(v[kf * 4 + h * 2], v[kf * 4 + h * 2 + 1], s);
    uint4* dst = (uint4*)(g_Yf + (size_t)tn * 256 + l * 8);
    dst[0] = make_uint4(o[0], o[1], o[2], o[3]);
    dst[1] = make_uint4(o[4], o[5], o[6], o[7]);
}

__global__ void prep_b(const float* __restrict__ b) {
    int t = blockIdx.x * 128 + threadIdx.x;
    int u = t >> 5, l = t & 31;
    int tile = u >> 3, fp = u & 7, kf = fp >> 1, nb2 = fp & 1;
    int c = nb2 * 8 + (l >> 2);
    int jb = tile * 64 + kf * 16 + 2 * (l & 3);
    float p0 = b[(size_t)jb * 16 + c];
    float p1 = b[(size_t)(jb + 1) * 16 + c];
    float p2 = b[(size_t)(jb + 8) * 16 + c];
    float p3 = b[(size_t)(jb + 9) * 16 + c];
    uint32_t h0 = pk_split(p0, p1, 0), h1 = pk_split(p2, p3, 0);
    uint32_t l0 = pk_split(p0, p1, 1), l1 = pk_split(p2, p3, 1);
    *(uint4*)(g_Bf + (size_t)tile * 1024 + fp * 128 + l * 4) = make_uint4(h0, h1, l0, l1);
}

// ================= main kernel: 4 warps x 32 i-rows = 128 i-rows/CTA =================
#define SMEM_BYTES 25088

__device__ __forceinline__ void issue_loads(uint32_t smb, int tile, int buf, int tid) {
    const char* gy = (const char*)g_Yf + (size_t)tile * 8192;
    uint32_t dy = smb + buf * 8192;
#pragma unroll
    for (int k = 0; k < 4; k++) cp16(dy + (tid + k * 128) * 16, gy + (size_t)(tid + k * 128) * 16);
    const char* gb = (const char*)g_Bf + (size_t)tile * 4096;
    uint32_t db = smb + 16384 + buf * 4096;
#pragma unroll
    for (int k = 0; k < 2; k++) cp16(db + (tid + k * 128) * 16, gb + (size_t)(tid + k * 128) * 16);
    if (tid < 16) cp16(smb + 24576 + buf * 256 + tid * 16, (const char*)(g_cyn + tile * 64) + tid * 16);
}

__global__ void __launch_bounds__(128, 4)
rbf_main(const float* __restrict__ ls) {
    __shared__ __align__(16) char sm[SMEM_BYTES];
    const uint32_t smb = smem_u32(sm);
    const int tid = threadIdx.x, w = tid >> 5, l = tid & 31;
    const int bidx = blockIdx.x;           // i-block 0..127 (128 rows each)
    const int sl = blockIdx.y;             // j-slice 0..8
    const int tstart = (sl < 4) ? 29 * sl : (116 + 28 * (sl - 4));
    const int tcnt = (sl < 4) ? 29 : 28;
    const int ig = bidx * 128 + w * 32;    // first i-row of this warp's 32

    uint32_t xfA[16], xfB[16];
    {
        const uint4* pA = (const uint4*)(g_Xf + ((size_t)(bidx * 8 + 2 * w) * 32 + l) * 16);
        const uint4* pB = (const uint4*)(g_Xf + ((size_t)(bidx * 8 + 2 * w + 1) * 32 + l) * 16);
#pragma unroll
        for (int q = 0; q < 4; q++) { *(uint4*)(xfA + 4 * q) = pA[q]; *(uint4*)(xfB + 4 * q) = pB[q]; }
    }
    const float cxnA0 = g_cxn[ig + (l >> 2)];
    const float cxnA1 = g_cxn[ig + (l >> 2) + 8];
    const float cxnB0 = g_cxn[ig + (l >> 2) + 16];
    const float cxnB1 = g_cxn[ig + (l >> 2) + 24];
    const float C2 = 2.f * __ldg(ls) * LOG2E;

    float o0A[4] = {0.f, 0.f, 0.f, 0.f}, o1A[4] = {0.f, 0.f, 0.f, 0.f};
    float o0B[4] = {0.f, 0.f, 0.f, 0.f}, o1B[4] = {0.f, 0.f, 0.f, 0.f};

    issue_loads(smb, tstart, 0, tid);
    CP_COMMIT();

    for (int tt = 0; tt < tcnt; tt++) {
        CP_WAIT0();
        __syncthreads();
        if (tt + 1 < tcnt) { issue_loads(smb, tstart + tt + 1, (tt + 1) & 1, tid); CP_COMMIT(); }
        const int buf = tt & 1;
        const char* syb = sm + buf * 8192;
        const char* sbb = sm + 16384 + buf * 4096;
        const char* scy = sm + 24576 + buf * 256;

        // double-slot register staging for the g-pipeline
        uint4 yv[2][4];     // [slot][h*2 + half]
        uint4 bv[2][2];
        float2 cyv[2][2];

#define LOADG(gg, slot) do { \
            const char* yb0 = syb + ((gg) * 2) * 1024 + l * 32; \
            const char* yb1 = syb + ((gg) * 2 + 1) * 1024 + l * 32; \
            yv[slot][0] = *(const uint4*)yb0; \
            yv[slot][1] = *(const uint4*)(yb0 + 16); \
            yv[slot][2] = *(const uint4*)yb1; \
            yv[slot][3] = *(const uint4*)(yb1 + 16); \
            bv[slot][0] = *(const uint4*)(sbb + ((gg) * 2) * 512 + l * 16); \
            bv[slot][1] = *(const uint4*)(sbb + ((gg) * 2 + 1) * 512 + l * 16); \
            cyv[slot][0] = *(const float2*)(scy + ((gg) * 2) * 32 + (l & 3) * 8); \
            cyv[slot][1] = *(const float2*)(scy + ((gg) * 2 + 1) * 32 + (l & 3) * 8); \
        } while (0)

        LOADG(w & 3, 0);   // warp-staggered start group

#pragma unroll
        for (int gg = 0; gg < 4; gg++) {
            const int p = gg & 1, q = p ^ 1;
            uint32_t wahA[4], walA[4], wahB[4], walB[4];
            // ---- GEMM1 bursts: h0 then h1, 4 chains round-robin each ----
            float sA0[4] = {0.f, 0.f, 0.f, 0.f}, sA1[4] = {0.f, 0.f, 0.f, 0.f};
            float sB0[4] = {0.f, 0.f, 0.f, 0.f}, sB1[4] = {0.f, 0.f, 0.f, 0.f};
            float tA0[4] = {0.f, 0.f, 0.f, 0.f}, tA1[4] = {0.f, 0.f, 0.f, 0.f};
            float tB0[4] = {0.f, 0.f, 0.f, 0.f}, tB1[4] = {0.f, 0.f, 0.f, 0.f};
            {
                uint4 y0 = yv[p][0], y1 = yv[p][1];
                mma_bf16(sA0, xfA + 0,  y0.x, y0.y);
                mma_bf16(sB0, xfB + 0,  y0.x, y0.y);
                mma_bf16(sA1, xfA + 4,  y0.z, y0.w);
                mma_bf16(sB1, xfB + 4,  y0.z, y0.w);
                mma_bf16(sA0, xfA + 0,  y1.x, y1.y);
                mma_bf16(sB0, xfB + 0,  y1.x, y1.y);
                mma_bf16(sA1, xfA + 4,  y1.z, y1.w);
                mma_bf16(sB1, xfB + 4,  y1.z, y1.w);
                mma_bf16(sA0, xfA + 8,  y0.x, y0.y);
                mma_bf16(sB0, xfB + 8,  y0.x, y0.y);
                mma_bf16(sA1, xfA + 12, y0.z, y0.w);
                mma_bf16(sB1, xfB + 12, y0.z, y0.w);
            }
            {
                uint4 y0 = yv[p][2], y1 = yv[p][3];
                mma_bf16(tA0, xfA + 0,  y0.x, y0.y);
                mma_bf16(tB0, xfB + 0,  y0.x, y0.y);
                mma_bf16(tA1, xfA + 4,  y0.z, y0.w);
                mma_bf16(tB1, xfB + 4,  y0.z, y0.w);
                mma_bf16(tA0, xfA + 0,  y1.x, y1.y);
                mma_bf16(tB0, xfB + 0,  y1.x, y1.y);
                mma_bf16(tA1, xfA + 4,  y1.z, y1.w);
                mma_bf16(tB1, xfB + 4,  y1.z, y1.w);
                mma_bf16(tA0, xfA + 8,  y0.x, y0.y);
                mma_bf16(tB0, xfB + 8,  y0.x, y0.y);
                mma_bf16(tA1, xfA + 12, y0.z, y0.w);
                mma_bf16(tB1, xfB + 12, y0.z, y0.w);
            }

            // ---- prefetch next rotated group (LDS hides under epilogues) ----
            if (gg < 3) LOADG((gg + 1 + w) & 3, q);

            // ---- epilogue h0 ----
            {
                float2 cy = cyv[p][0];
                float w0 = ex2f(fminf(fmaf(C2, sA0[0] + sA1[0], cxnA0 + cy.x), 0.f));
                float w1 = ex2f(fminf(fmaf(C2, sA0[1] + sA1[1], cxnA0 + cy.y), 0.f));
                float w2 = ex2f(fminf(fmaf(C2, sA0[2] + sA1[2], cxnA1 + cy.x), 0.f));
                float w3 = ex2f(fminf(fmaf(C2, sA0[3] + sA1[3], cxnA1 + cy.y), 0.f));
                uint32_t h01 = pk2(w0, w1), h23 = pk2(w2, w3);
                wahA[0] = h01; wahA[1] = h23;
                walA[0] = pk2(w0 - bflo(h01), w1 - bfhi(h01));
                walA[1] = pk2(w2 - bflo(h23), w3 - bfhi(h23));
                float v0 = ex2f(fminf(fmaf(C2, sB0[0] + sB1[0], cxnB0 + cy.x), 0.f));
                float v1 = ex2f(fminf(fmaf(C2, sB0[1] + sB1[1], cxnB0 + cy.y), 0.f));
                float v2 = ex2f(fminf(fmaf(C2, sB0[2] + sB1[2], cxnB1 + cy.x), 0.f));
                float v3 = ex2f(fminf(fmaf(C2, sB0[3] + sB1[3], cxnB1 + cy.y), 0.f));
                uint32_t g01 = pk2(v0, v1), g23 = pk2(v2, v3);
                wahB[0] = g01; wahB[1] = g23;
                walB[0] = pk2(v0 - bflo(g01), v1 - bfhi(g01));
                walB[1] = pk2(v2 - bflo(g23), v3 - bfhi(g23));
            }
            // ---- epilogue h1 ----
            {
                float2 cy = cyv[p][1];
                float w0 = ex2f(fminf(fmaf(C2, tA0[0] + tA1[0], cxnA0 + cy.x), 0.f));
                float w1 = ex2f(fminf(fmaf(C2, tA0[1] + tA1[1], cxnA0 + cy.y), 0.f));
                float w2 = ex2f(fminf(fmaf(C2, tA0[2] + tA1[2], cxnA1 + cy.x), 0.f));
                float w3 = ex2f(fminf(fmaf(C2, tA0[3] + tA1[3], cxnA1 + cy.y), 0.f));
                uint32_t h01 = pk2(w0, w1), h23 = pk2(w2, w3);
                wahA[2] = h01; wahA[3] = h23;
                walA[2] = pk2(w0 - bflo(h01), w1 - bfhi(h01));
                walA[3] = pk2(w2 - bflo(h23), w3 - bfhi(h23));
                float v0 = ex2f(fminf(fmaf(C2, tB0[0] + tB1[0], cxnB0 + cy.x), 0.f));
                float v1 = ex2f(fminf(fmaf(C2, tB0[1] + tB1[1], cxnB0 + cy.y), 0.f));
                float v2 = ex2f(fminf(fmaf(C2, tB0[2] + tB1[2], cxnB1 + cy.x), 0.f));
                float v3 = ex2f(fminf(fmaf(C2, tB0[3] + tB1[3], cxnB1 + cy.y), 0.f));
                uint32_t g01 = pk2(v0, v1), g23 = pk2(v2, v3);
                wahB[2] = g01; wahB[3] = g23;
                walB[2] = pk2(v0 - bflo(g01), v1 - bfhi(g01));
                walB[3] = pk2(v2 - bflo(g23), v3 - bfhi(g23));
            }
            // ---- GEMM2: 4 accumulator chains round-robin ----
            uint4 b0 = bv[p][0], b1 = bv[p][1];
            mma_bf16(o0A, wahA, b0.x, b0.y);
            mma_bf16(o0B, wahB, b0.x, b0.y);
            mma_bf16(o1A, wahA, b1.x, b1.y);
            mma_bf16(o1B, wahB, b1.x, b1.y);
            mma_bf16(o0A, wahA, b0.z, b0.w);
            mma_bf16(o0B, wahB, b0.z, b0.w);
            mma_bf16(o1A, wahA, b1.z, b1.w);
            mma_bf16(o1B, wahB, b1.z, b1.w);
            mma_bf16(o0A, walA, b0.x, b0.y);
            mma_bf16(o0B, walB, b0.x, b0.y);
            mma_bf16(o1A, walA, b1.x, b1.y);
            mma_bf16(o1B, walB, b1.x, b1.y);
        }
#undef LOADG
    }

    // partial write: slice-local buffer
    float* op = g_Op + (size_t)sl * (NP * 16);
    const int cb = 2 * (l & 3);
    const int rA = ig + (l >> 2), rB = rA + 16;
    *(float2*)(op + (size_t)rA * 16 + cb)            = make_float2(o0A[0], o0A[1]);
    *(float2*)(op + (size_t)rA * 16 + 8 + cb)        = make_float2(o1A[0], o1A[1]);
    *(float2*)(op + (size_t)(rA + 8) * 16 + cb)      = make_float2(o0A[2], o0A[3]);
    *(float2*)(op + (size_t)(rA + 8) * 16 + 8 + cb)  = make_float2(o1A[2], o1A[3]);
    *(float2*)(op + (size_t)rB * 16 + cb)            = make_float2(o0B[0], o0B[1]);
    *(float2*)(op + (size_t)rB * 16 + 8 + cb)        = make_float2(o1B[0], o1B[1]);
    *(float2*)(op + (size_t)(rB + 8) * 16 + cb)      = make_float2(o0B[2], o0B[3]);
    *(float2*)(op + (size_t)(rB + 8) * 16 + 8 + cb)  = make_float2(o1B[2], o1B[3]);
}

// ================= deterministic slice reduction =================
__global__ void reduce_k(float* __restrict__ out) {
    int idx = blockIdx.x * 256 + threadIdx.x;
    float4 o = ((const float4*)g_Op)[idx];
#pragma unroll
    for (int s = 1; s < NSL; s++) {
        float4 v = ((const float4*)(g_Op + (size_t)s * NP * 16))[idx];
        o.x += v.x; o.y += v.y; o.z += v.z; o.w += v.w;   // fixed slice order
    }
    ((float4*)out)[idx] = o;
}

extern "C" void kernel_launch(void* const* d_in, const int* in_sizes, int n_in,
                              void* d_out, int out_size) {
    const float* ls = (const float*)d_in[0];
    const float* x  = (const float*)d_in[1];
    const float* y  = (const float*)d_in[2];
    const float* b  = (const float*)d_in[3];
    float* out = (float*)d_out;

    prep_x<<<256, 128>>>(ls, x);
    prep_y<<<512, 128>>>(ls, y);
    prep_b<<<512, 128>>>(b);
    rbf_main<<<dim3(128, NSL), 128>>>(ls);
    reduce_k<<<256, 256>>>(out);
}

// round 12
// speedup vs baseline: 1.0109x; 1.0109x over previous
#include <cuda_runtime.h>
#include <cuda_bf16.h>
#include <cstdint>

#define LOG2E 1.4426950408889634f
#define NP  16384
#define NT  256      // j-tiles of 64
#define NWG 1024     // i row-groups of 16
#define NSL 9        // j-slices: 4x29 + 5x28 = 256

// ---- static device scratch (no allocation) ----
__device__ uint32_t g_Xf[NWG * 32 * 16];  // a-frag image
__device__ uint32_t g_Yf[NT * 2048];      // b-frag image (GEMM1)
__device__ uint32_t g_Bf[NT * 1024];      // b-frag image (GEMM2)
__device__ float g_cxn[NP];
__device__ float g_cyn[NP];
__device__ float g_Op[NSL * NP * 16];     // per-slice fp32 partials (9 MB)

// ---- helpers ----
__device__ __forceinline__ uint32_t smem_u32(const void* p) {
    uint32_t a;
    asm("{ .reg .u64 t; cvta.to.shared.u64 t, %1; cvt.u32.u64 %0, t; }" : "=r"(a) : "l"(p));
    return a;
}
__device__ __forceinline__ void cp16(uint32_t d, const void* s) {
    asm volatile("cp.async.cg.shared.global [%0], [%1], 16;" :: "r"(d), "l"(s));
}
#define CP_COMMIT() asm volatile("cp.async.commit_group;" ::: "memory")
#define CP_WAIT0()  asm volatile("cp.async.wait_group 0;" ::: "memory")

__device__ __forceinline__ void mma_bf16(float* d, const uint32_t* a, uint32_t b0, uint32_t b1) {
    asm volatile("mma.sync.aligned.m16n8k16.row.col.f32.bf16.bf16.f32 "
                 "{%0,%1,%2,%3},{%4,%5,%6,%7},{%8,%9},{%0,%1,%2,%3};"
                 : "+f"(d[0]), "+f"(d[1]), "+f"(d[2]), "+f"(d[3])
                 : "r"(a[0]), "r"(a[1]), "r"(a[2]), "r"(a[3]), "r"(b0), "r"(b1));
}
__device__ __forceinline__ float ex2f(float a) {
    float r; asm("ex2.approx.ftz.f32 %0, %1;" : "=f"(r) : "f"(a)); return r;
}
__device__ __forceinline__ uint32_t pk2(float lo, float hi) {
    __nv_bfloat162 h = __float22bfloat162_rn(make_float2(lo, hi));
    return *(uint32_t*)&h;
}
__device__ __forceinline__ float bflo(uint32_t u) { return __uint_as_float(u << 16); }
__device__ __forceinline__ float bfhi(uint32_t u) { return __uint_as_float(u & 0xffff0000u); }
__device__ __forceinline__ uint32_t pk_split(float a, float b, int low) {
    float ah = __bfloat162float(__float2bfloat16(a));
    float bh = __bfloat162float(__float2bfloat16(b));
    return low ? pk2(a - ah, b - bh) : pk2(ah, bh);
}

// ================= prep kernels (unchanged from R9) =================
__global__ void prep_x(const float* __restrict__ ls, const float* __restrict__ x) {
    int t = blockIdx.x * 128 + threadIdx.x;
    int wg = t >> 5, l = t & 31;
    int r0 = wg * 16 + (l >> 2), r1 = r0 + 8;
    int c = 2 * (l & 3);
    const float* x0 = x + (size_t)r0 * 32;
    const float* x1 = x + (size_t)r1 * 32;
    float v0[8], v1[8], n0 = 0.f, n1 = 0.f;
#pragma unroll
    for (int kf = 0; kf < 2; kf++)
#pragma unroll
        for (int h = 0; h < 2; h++)
#pragma unroll
            for (int e = 0; e < 2; e++) {
                int idx = kf * 4 + h * 2 + e;
                int col = kf * 16 + h * 8 + c + e;
                v0[idx] = x0[col]; v1[idx] = x1[col];
                n0 += v0[idx] * v0[idx];
                n1 += v1[idx] * v1[idx];
            }
    n0 += __shfl_xor_sync(0xffffffffu, n0, 1); n0 += __shfl_xor_sync(0xffffffffu, n0, 2);
    n1 += __shfl_xor_sync(0xffffffffu, n1, 1); n1 += __shfl_xor_sync(0xffffffffu, n1, 2);
    const float cneg = -ls[0] * LOG2E;
    if ((l & 3) == 0) { g_cxn[r0] = cneg * n0; g_cxn[r1] = cneg * n1; }

    uint32_t o[16];
#pragma unroll
    for (int s = 0; s < 2; s++)
#pragma unroll
        for (int kf = 0; kf < 2; kf++)
#pragma unroll
            for (int h = 0; h < 2; h++) {
                o[s * 8 + kf * 4 + h * 2 + 0] = pk_split(v0[kf * 4 + h * 2], v0[kf * 4 + h * 2 + 1], s);
                o[s * 8 + kf * 4 + h * 2 + 1] = pk_split(v1[kf * 4 + h * 2], v1[kf * 4 + h * 2 + 1], s);
            }
    uint4* dst = (uint4*)(g_Xf + (size_t)t * 16);
#pragma unroll
    for (int q = 0; q < 4; q++) dst[q] = make_uint4(o[4 * q], o[4 * q + 1], o[4 * q + 2], o[4 * q + 3]);
}

__global__ void prep_y(const float* __restrict__ ls, const float* __restrict__ y) {
    int t = blockIdx.x * 128 + threadIdx.x;
    int tn = t >> 5, l = t & 31;
    int j = tn * 8 + (l >> 2);
    int c = 2 * (l & 3);
    const float* yr = y + (size_t)j * 32;
    float v[8], n = 0.f;
#pragma unroll
    for (int kf = 0; kf < 2; kf++)
#pragma unroll
        for (int h = 0; h < 2; h++)
#pragma unroll
            for (int e = 0; e < 2; e++) {
                int idx = kf * 4 + h * 2 + e;
                v[idx] = yr[kf * 16 + h * 8 + c + e];
                n += v[idx] * v[idx];
            }
    n += __shfl_xor_sync(0xffffffffu, n, 1); n += __shfl_xor_sync(0xffffffffu, n, 2);
    if ((l & 3) == 0) g_cyn[j] = -ls[0] * LOG2E * n;

    uint32_t o[8];
#pragma unroll
    for (int s = 0; s < 2; s++)
#pragma unroll
        for (int kf = 0; kf < 2; kf++)
#pragma unroll
            for (int h = 0; h < 2; h++)
                o[s * 4 + kf * 2 + h] = pk_split(v[kf * 4 + h * 2], v[kf * 4 + h * 2 + 1], s);
    uint4* dst = (uint4*)(g_Yf + (size_t)tn * 256 + l * 8);
    dst[0] = make_uint4(o[0], o[1], o[2], o[3]);
    dst[1] = make_uint4(o[4], o[5], o[6], o[7]);
}

__global__ void prep_b(const float* __restrict__ b) {
    int t = blockIdx.x * 128 + threadIdx.x;
    int u = t >> 5, l = t & 31;
    int tile = u >> 3, fp = u & 7, kf = fp >> 1, nb2 = fp & 1;
    int c = nb2 * 8 + (l >> 2);
    int jb = tile * 64 + kf * 16 + 2 * (l & 3);
    float p0 = b[(size_t)jb * 16 + c];
    float p1 = b[(size_t)(jb + 1) * 16 + c];
    float p2 = b[(size_t)(jb + 8) * 16 + c];
    float p3 = b[(size_t)(jb + 9) * 16 + c];
    uint32_t h0 = pk_split(p0, p1, 0), h1 = pk_split(p2, p3, 0);
    uint32_t l0 = pk_split(p0, p1, 1), l1 = pk_split(p2, p3, 1);
    *(uint4*)(g_Bf + (size_t)tile * 1024 + fp * 128 + l * 4) = make_uint4(h0, h1, l0, l1);
}

// ================= main kernel: 4 warps x 32 i-rows = 128 i-rows/CTA =================
#define SMEM_BYTES 25088

__device__ __forceinline__ void issue_loads(uint32_t smb, int tile, int buf, int tid) {
    const char* gy = (const char*)g_Yf + (size_t)tile * 8192;
    uint32_t dy = smb + buf * 8192;
#pragma unroll
    for (int k = 0; k < 4; k++) cp16(dy + (tid + k * 128) * 16, gy + (size_t)(tid + k * 128) * 16);
    const char* gb = (const char*)g_Bf + (size_t)tile * 4096;
    uint32_t db = smb + 16384 + buf * 4096;
#pragma unroll
    for (int k = 0; k < 2; k++) cp16(db + (tid + k * 128) * 16, gb + (size_t)(tid + k * 128) * 16);
    if (tid < 16) cp16(smb + 24576 + buf * 256 + tid * 16, (const char*)(g_cyn + tile * 64) + tid * 16);
}

__global__ void __launch_bounds__(128, 4)
rbf_main(const float* __restrict__ ls) {
    __shared__ __align__(16) char sm[SMEM_BYTES];
    const uint32_t smb = smem_u32(sm);
    const int tid = threadIdx.x, w = tid >> 5, l = tid & 31;
    const int bidx = blockIdx.x;           // i-block 0..127 (128 rows each)
    const int sl = blockIdx.y;             // j-slice 0..8
    const int tstart = (sl < 4) ? 29 * sl : (116 + 28 * (sl - 4));
    const int tcnt = (sl < 4) ? 29 : 28;
    const int ig = bidx * 128 + w * 32;    // first i-row of this warp's 32

    uint32_t xfA[16], xfB[16];
    {
        const uint4* pA = (const uint4*)(g_Xf + ((size_t)(bidx * 8 + 2 * w) * 32 + l) * 16);
        const uint4* pB = (const uint4*)(g_Xf + ((size_t)(bidx * 8 + 2 * w + 1) * 32 + l) * 16);
#pragma unroll
        for (int q = 0; q < 4; q++) { *(uint4*)(xfA + 4 * q) = pA[q]; *(uint4*)(xfB + 4 * q) = pB[q]; }
    }
    const float cxnA0 = g_cxn[ig + (l >> 2)];
    const float cxnA1 = g_cxn[ig + (l >> 2) + 8];
    const float cxnB0 = g_cxn[ig + (l >> 2) + 16];
    const float cxnB1 = g_cxn[ig + (l >> 2) + 24];
    const float C2 = 2.f * __ldg(ls) * LOG2E;

    float o0A[4] = {0.f, 0.f, 0.f, 0.f}, o1A[4] = {0.f, 0.f, 0.f, 0.f};
    float o0B[4] = {0.f, 0.f, 0.f, 0.f}, o1B[4] = {0.f, 0.f, 0.f, 0.f};

    // pipeline registers carried across groups AND tiles
    uint4 yv[2][4];          // [slot][h*2 + half]
    uint4 bv[2][2];          // [slot][half]
    float2 cyv[2][2];
    uint32_t wahA[4], walA[4], wahB[4], walB[4];  // W frags of the PREVIOUS group

    issue_loads(smb, tstart, 0, tid);
    CP_COMMIT();

#define LOADG(gg, slot) do { \
        const char* yb0 = syb + ((gg) * 2) * 1024 + l * 32; \
        const char* yb1 = syb + ((gg) * 2 + 1) * 1024 + l * 32; \
        yv[slot][0] = *(const uint4*)yb0; \
        yv[slot][1] = *(const uint4*)(yb0 + 16); \
        yv[slot][2] = *(const uint4*)yb1; \
        yv[slot][3] = *(const uint4*)(yb1 + 16); \
        bv[slot][0] = *(const uint4*)(sbb + ((gg) * 2) * 512 + l * 16); \
        bv[slot][1] = *(const uint4*)(sbb + ((gg) * 2 + 1) * 512 + l * 16); \
        cyv[slot][0] = *(const float2*)(scy + ((gg) * 2) * 32 + (l & 3) * 8); \
        cyv[slot][1] = *(const float2*)(scy + ((gg) * 2 + 1) * 32 + (l & 3) * 8); \
    } while (0)

#define GEMM2(bb0, bb1) do { \
        mma_bf16(o0A, wahA, (bb0).x, (bb0).y); \
        mma_bf16(o0B, wahB, (bb0).x, (bb0).y); \
        mma_bf16(o1A, wahA, (bb1).x, (bb1).y); \
        mma_bf16(o1B, wahB, (bb1).x, (bb1).y); \
        mma_bf16(o0A, wahA, (bb0).z, (bb0).w); \
        mma_bf16(o0B, wahB, (bb0).z, (bb0).w); \
        mma_bf16(o1A, wahA, (bb1).z, (bb1).w); \
        mma_bf16(o1B, wahB, (bb1).z, (bb1).w); \
        mma_bf16(o0A, walA, (bb0).x, (bb0).y); \
        mma_bf16(o0B, walB, (bb0).x, (bb0).y); \
        mma_bf16(o1A, walA, (bb1).x, (bb1).y); \
        mma_bf16(o1B, walB, (bb1).x, (bb1).y); \
    } while (0)

    for (int tt = 0; tt < tcnt; tt++) {
        CP_WAIT0();
        __syncthreads();
        if (tt + 1 < tcnt) { issue_loads(smb, tstart + tt + 1, (tt + 1) & 1, tid); CP_COMMIT(); }
        const int buf = tt & 1;
        const char* syb = sm + buf * 8192;
        const char* sbb = sm + 16384 + buf * 4096;
        const char* scy = sm + 24576 + buf * 256;

        LOADG(0, 0);

#pragma unroll
        for (int g = 0; g < 4; g++) {
            const int p = g & 1, q = p ^ 1;
            // ---- GEMM1 burst for group g: 24 MMAs, 8 chains round-robin ----
            float sA0[4] = {0.f, 0.f, 0.f, 0.f}, sA1[4] = {0.f, 0.f, 0.f, 0.f};
            float sB0[4] = {0.f, 0.f, 0.f, 0.f}, sB1[4] = {0.f, 0.f, 0.f, 0.f};
            float tA0[4] = {0.f, 0.f, 0.f, 0.f}, tA1[4] = {0.f, 0.f, 0.f, 0.f};
            float tB0[4] = {0.f, 0.f, 0.f, 0.f}, tB1[4] = {0.f, 0.f, 0.f, 0.f};
            {
                uint4 y0 = yv[p][0], y1 = yv[p][1];
                mma_bf16(sA0, xfA + 0,  y0.x, y0.y);
                mma_bf16(sB0, xfB + 0,  y0.x, y0.y);
                mma_bf16(sA1, xfA + 4,  y0.z, y0.w);
                mma_bf16(sB1, xfB + 4,  y0.z, y0.w);
                mma_bf16(sA0, xfA + 0,  y1.x, y1.y);
                mma_bf16(sB0, xfB + 0,  y1.x, y1.y);
                mma_bf16(sA1, xfA + 4,  y1.z, y1.w);
                mma_bf16(sB1, xfB + 4,  y1.z, y1.w);
                mma_bf16(sA0, xfA + 8,  y0.x, y0.y);
                mma_bf16(sB0, xfB + 8,  y0.x, y0.y);
                mma_bf16(sA1, xfA + 12, y0.z, y0.w);
                mma_bf16(sB1, xfB + 12, y0.z, y0.w);
            }
            {
                uint4 y0 = yv[p][2], y1 = yv[p][3];
                mma_bf16(tA0, xfA + 0,  y0.x, y0.y);
                mma_bf16(tB0, xfB + 0,  y0.x, y0.y);
                mma_bf16(tA1, xfA + 4,  y0.z, y0.w);
                mma_bf16(tB1, xfB + 4,  y0.z, y0.w);
                mma_bf16(tA0, xfA + 0,  y1.x, y1.y);
                mma_bf16(tB0, xfB + 0,  y1.x, y1.y);
                mma_bf16(tA1, xfA + 4,  y1.z, y1.w);
                mma_bf16(tB1, xfB + 4,  y1.z, y1.w);
                mma_bf16(tA0, xfA + 8,  y0.x, y0.y);
                mma_bf16(tB0, xfB + 8,  y0.x, y0.y);
                mma_bf16(tA1, xfA + 12, y0.z, y0.w);
                mma_bf16(tB1, xfB + 12, y0.z, y0.w);
            }

            // ---- GEMM2 for PREVIOUS group (wah/wal + bv[q] from last iteration) ----
            if (g > 0) {
                GEMM2(bv[q][0], bv[q][1]);
            } else if (tt > 0) {
                GEMM2(bv[1][0], bv[1][1]);   // group 3 of previous tile (slot 1)
            }

            // ---- prefetch next group (LDS hides under epilogues) ----
            if (g < 3) LOADG(g + 1, q);

            // ---- epilogue h0 (writes wah/wal for THIS group) ----
            {
                float2 cy = cyv[p][0];
                float w0 = ex2f(fminf(fmaf(C2, sA0[0] + sA1[0], cxnA0 + cy.x), 0.f));
                float w1 = ex2f(fminf(fmaf(C2, sA0[1] + sA1[1], cxnA0 + cy.y), 0.f));
                float w2 = ex2f(fminf(fmaf(C2, sA0[2] + sA1[2], cxnA1 + cy.x), 0.f));
                float w3 = ex2f(fminf(fmaf(C2, sA0[3] + sA1[3], cxnA1 + cy.y), 0.f));
                uint32_t h01 = pk2(w0, w1), h23 = pk2(w2, w3);
                wahA[0] = h01; wahA[1] = h23;
                walA[0] = pk2(w0 - bflo(h01), w1 - bfhi(h01));
                walA[1] = pk2(w2 - bflo(h23), w3 - bfhi(h23));
                float v0 = ex2f(fminf(fmaf(C2, sB0[0] + sB1[0], cxnB0 + cy.x), 0.f));
                float v1 = ex2f(fminf(fmaf(C2, sB0[1] + sB1[1], cxnB0 + cy.y), 0.f));
                float v2 = ex2f(fminf(fmaf(C2, sB0[2] + sB1[2], cxnB1 + cy.x), 0.f));
                float v3 = ex2f(fminf(fmaf(C2, sB0[3] + sB1[3], cxnB1 + cy.y), 0.f));
                uint32_t g01 = pk2(v0, v1), g23 = pk2(v2, v3);
                wahB[0] = g01; wahB[1] = g23;
                walB[0] = pk2(v0 - bflo(g01), v1 - bfhi(g01));
                walB[1] = pk2(v2 - bflo(g23), v3 - bfhi(g23));
            }
            // ---- epilogue h1 ----
            {
                float2 cy = cyv[p][1];
                float w0 = ex2f(fminf(fmaf(C2, tA0[0] + tA1[0], cxnA0 + cy.x), 0.f));
                float w1 = ex2f(fminf(fmaf(C2, tA0[1] + tA1[1], cxnA0 + cy.y), 0.f));
                float w2 = ex2f(fminf(fmaf(C2, tA0[2] + tA1[2], cxnA1 + cy.x), 0.f));
                float w3 = ex2f(fminf(fmaf(C2, tA0[3] + tA1[3], cxnA1 + cy.y), 0.f));
                uint32_t h01 = pk2(w0, w1), h23 = pk2(w2, w3);
                wahA[2] = h01; wahA[3] = h23;
                walA[2] = pk2(w0 - bflo(h01), w1 - bfhi(h01));
                walA[3] = pk2(w2 - bflo(h23), w3 - bfhi(h23));
                float v0 = ex2f(fminf(fmaf(C2, tB0[0] + tB1[0], cxnB0 + cy.x), 0.f));
                float v1 = ex2f(fminf(fmaf(C2, tB0[1] + tB1[1], cxnB0 + cy.y), 0.f));
                float v2 = ex2f(fminf(fmaf(C2, tB0[2] + tB1[2], cxnB1 + cy.x), 0.f));
                float v3 = ex2f(fminf(fmaf(C2, tB0[3] + tB1[3], cxnB1 + cy.y), 0.f));
                uint32_t g01 = pk2(v0, v1), g23 = pk2(v2, v3);
                wahB[2] = g01; wahB[3] = g23;
                walB[2] = pk2(v0 - bflo(g01), v1 - bfhi(g01));
                walB[3] = pk2(v2 - bflo(g23), v3 - bfhi(g23));
            }
        }
    }

    // ---- pipeline drain: GEMM2 for the final group (slot 1) ----
    GEMM2(bv[1][0], bv[1][1]);

#undef GEMM2
#undef LOADG

    // partial write: slice-local buffer
    float* op = g_Op + (size_t)sl * (NP * 16);
    const int cb = 2 * (l & 3);
    const int rA = ig + (l >> 2), rB = rA + 16;
    *(float2*)(op + (size_t)rA * 16 + cb)            = make_float2(o0A[0], o0A[1]);
    *(float2*)(op + (size_t)rA * 16 + 8 + cb)        = make_float2(o1A[0], o1A[1]);
    *(float2*)(op + (size_t)(rA + 8) * 16 + cb)      = make_float2(o0A[2], o0A[3]);
    *(float2*)(op + (size_t)(rA + 8) * 16 + 8 + cb)  = make_float2(o1A[2], o1A[3]);
    *(float2*)(op + (size_t)rB * 16 + cb)            = make_float2(o0B[0], o0B[1]);
    *(float2*)(op + (size_t)rB * 16 + 8 + cb)        = make_float2(o1B[0], o1B[1]);
    *(float2*)(op + (size_t)(rB + 8) * 16 + cb)      = make_float2(o0B[2], o0B[3]);
    *(float2*)(op + (size_t)(rB + 8) * 16 + 8 + cb)  = make_float2(o1B[2], o1B[3]);
}

// ================= deterministic slice reduction =================
__global__ void reduce_k(float* __restrict__ out) {
    int idx = blockIdx.x * 256 + threadIdx.x;
    float4 o = ((const float4*)g_Op)[idx];
#pragma unroll
    for (int s = 1; s < NSL; s++) {
        float4 v = ((const float4*)(g_Op + (size_t)s * NP * 16))[idx];
        o.x += v.x; o.y += v.y; o.z += v.z; o.w += v.w;   // fixed slice order
    }
    ((float4*)out)[idx] = o;
}

extern "C" void kernel_launch(void* const* d_in, const int* in_sizes, int n_in,
                              void* d_out, int out_size) {
    const float* ls = (const float*)d_in[0];
    const float* x  = (const float*)d_in[1];
    const float* y  = (const float*)d_in[2];
    const float* b  = (const float*)d_in[3];
    float* out = (float*)d_out;

    prep_x<<<256, 128>>>(ls, x);
    prep_y<<<512, 128>>>(ls, y);
    prep_b<<<512, 128>>>(b);
    rbf_main<<<dim3(128, NSL), 128>>>(ls);
    reduce_k<<<256, 256>>>(out);
}

// round 13
// speedup vs baseline: 1.0308x; 1.0197x over previous
#include <cuda_runtime.h>
#include <cuda_bf16.h>
#include <cstdint>

#define LOG2E 1.4426950408889634f
#define NP  16384
#define NT  256      // j-tiles of 64
#define NWG 1024     // i row-groups of 16
#define NSL 9        // j-slices: 4x29 + 5x28 = 256

// ---- static device scratch (no allocation) ----
__device__ uint32_t g_Xf[NWG * 32 * 16];  // a-frag image
__device__ uint32_t g_Yf[NT * 2048];      // b-frag image (GEMM1)
__device__ uint32_t g_Bf[NT * 1024];      // b-frag image (GEMM2)
__device__ float g_cxn[NP];
__device__ float g_cyn[NP];
__device__ float g_Op[NSL * NP * 16];     // per-slice fp32 partials (9 MB)

// ---- helpers ----
__device__ __forceinline__ uint32_t smem_u32(const void* p) {
    uint32_t a;
    asm("{ .reg .u64 t; cvta.to.shared.u64 t, %1; cvt.u32.u64 %0, t; }" : "=r"(a) : "l"(p));
    return a;
}
__device__ __forceinline__ void cp16(uint32_t d, const void* s) {
    asm volatile("cp.async.cg.shared.global [%0], [%1], 16;" :: "r"(d), "l"(s));
}
#define CP_COMMIT() asm volatile("cp.async.commit_group;" ::: "memory")
#define CP_WAIT0()  asm volatile("cp.async.wait_group 0;" ::: "memory")

__device__ __forceinline__ void mma_bf16(float* d, const uint32_t* a, uint32_t b0, uint32_t b1) {
    asm volatile("mma.sync.aligned.m16n8k16.row.col.f32.bf16.bf16.f32 "
                 "{%0,%1,%2,%3},{%4,%5,%6,%7},{%8,%9},{%0,%1,%2,%3};"
                 : "+f"(d[0]), "+f"(d[1]), "+f"(d[2]), "+f"(d[3])
                 : "r"(a[0]), "r"(a[1]), "r"(a[2]), "r"(a[3]), "r"(b0), "r"(b1));
}
__device__ __forceinline__ float ex2f(float a) {
    float r; asm("ex2.approx.ftz.f32 %0, %1;" : "=f"(r) : "f"(a)); return r;
}
__device__ __forceinline__ uint32_t pk2(float lo, float hi) {
    __nv_bfloat162 h = __float22bfloat162_rn(make_float2(lo, hi));
    return *(uint32_t*)&h;
}
__device__ __forceinline__ float bflo(uint32_t u) { return __uint_as_float(u << 16); }
__device__ __forceinline__ float bfhi(uint32_t u) { return __uint_as_float(u & 0xffff0000u); }
__device__ __forceinline__ uint32_t pk_split(float a, float b, int low) {
    float ah = __bfloat162float(__float2bfloat16(a));
    float bh = __bfloat162float(__float2bfloat16(b));
    return low ? pk2(a - ah, b - bh) : pk2(ah, bh);
}

// ================= prep kernels (unchanged) =================
__global__ void prep_x(const float* __restrict__ ls, const float* __restrict__ x) {
    int t = blockIdx.x * 128 + threadIdx.x;
    int wg = t >> 5, l = t & 31;
    int r0 = wg * 16 + (l >> 2), r1 = r0 + 8;
    int c = 2 * (l & 3);
    const float* x0 = x + (size_t)r0 * 32;
    const float* x1 = x + (size_t)r1 * 32;
    float v0[8], v1[8], n0 = 0.f, n1 = 0.f;
#pragma unroll
    for (int kf = 0; kf < 2; kf++)
#pragma unroll
        for (int h = 0; h < 2; h++)
#pragma unroll
            for (int e = 0; e < 2; e++) {
                int idx = kf * 4 + h * 2 + e;
                int col = kf * 16 + h * 8 + c + e;
                v0[idx] = x0[col]; v1[idx] = x1[col];
                n0 += v0[idx] * v0[idx];
                n1 += v1[idx] * v1[idx];
            }
    n0 += __shfl_xor_sync(0xffffffffu, n0, 1); n0 += __shfl_xor_sync(0xffffffffu, n0, 2);
    n1 += __shfl_xor_sync(0xffffffffu, n1, 1); n1 += __shfl_xor_sync(0xffffffffu, n1, 2);
    const float cneg = -ls[0] * LOG2E;
    if ((l & 3) == 0) { g_cxn[r0] = cneg * n0; g_cxn[r1] = cneg * n1; }

    uint32_t o[16];
#pragma unroll
    for (int s = 0; s < 2; s++)
#pragma unroll
        for (int kf = 0; kf < 2; kf++)
#pragma unroll
            for (int h = 0; h < 2; h++) {
                o[s * 8 + kf * 4 + h * 2 + 0] = pk_split(v0[kf * 4 + h * 2], v0[kf * 4 + h * 2 + 1], s);
                o[s * 8 + kf * 4 + h * 2 + 1] = pk_split(v1[kf * 4 + h * 2], v1[kf * 4 + h * 2 + 1], s);
            }
    uint4* dst = (uint4*)(g_Xf + (size_t)t * 16);
#pragma unroll
    for (int q = 0; q < 4; q++) dst[q] = make_uint4(o[4 * q], o[4 * q + 1], o[4 * q + 2], o[4 * q + 3]);
}

__global__ void prep_y(const float* __restrict__ ls, const float* __restrict__ y) {
    int t = blockIdx.x * 128 + threadIdx.x;
    int tn = t >> 5, l = t & 31;
    int j = tn * 8 + (l >> 2);
    int c = 2 * (l & 3);
    const float* yr = y + (size_t)j * 32;
    float v[8], n = 0.f;
#pragma unroll
    for (int kf = 0; kf < 2; kf++)
#pragma unroll
        for (int h = 0; h < 2; h++)
#pragma unroll
            for (int e = 0; e < 2; e++) {
                int idx = kf * 4 + h * 2 + e;
                v[idx] = yr[kf * 16 + h * 8 + c + e];
                n += v[idx] * v[idx];
            }
    n += __shfl_xor_sync(0xffffffffu, n, 1); n += __shfl_xor_sync(0xffffffffu, n, 2);
    if ((l & 3) == 0) g_cyn[j] = -ls[0] * LOG2E * n;

    uint32_t o[8];
#pragma unroll
    for (int s = 0; s < 2; s++)
#pragma unroll
        for (int kf = 0; kf < 2; kf++)
#pragma unroll
            for (int h = 0; h < 2; h++)
                o[s * 4 + kf * 2 + h] = pk_split(v[kf * 4 + h * 2], v[kf * 4 + h * 2 + 1], s);
    uint4* dst = (uint4*)(g_Yf + (size_t)tn * 256 + l * 8);
    dst[0] = make_uint4(o[0], o[1], o[2], o[3]);
    dst[1] = make_uint4(o[4], o[5], o[6], o[7]);
}

__global__ void prep_b(const float* __restrict__ b) {
    int t = blockIdx.x * 128 + threadIdx.x;
    int u = t >> 5, l = t & 31;
    int tile = u >> 3, fp = u & 7, kf = fp >> 1, nb2 = fp & 1;
    int c = nb2 * 8 + (l >> 2);
    int jb = tile * 64 + kf * 16 + 2 * (l & 3);
    float p0 = b[(size_t)jb * 16 + c];
    float p1 = b[(size_t)(jb + 1) * 16 + c];
    float p2 = b[(size_t)(jb + 8) * 16 + c];
    float p3 = b[(size_t)(jb + 9) * 16 + c];
    uint32_t h0 = pk_split(p0, p1, 0), h1 = pk_split(p2, p3, 0);
    uint32_t l0 = pk_split(p0, p1, 1), l1 = pk_split(p2, p3, 1);
    *(uint4*)(g_Bf + (size_t)tile * 1024 + fp * 128 + l * 4) = make_uint4(h0, h1, l0, l1);
}

// ================= main kernel: 4 warps x 32 i-rows = 128 i-rows/CTA, 5 CTAs/SM =================
#define SMEM_BYTES 25088

__device__ __forceinline__ void issue_loads(uint32_t smb, int tile, int buf, int tid) {
    const char* gy = (const char*)g_Yf + (size_t)tile * 8192;
    uint32_t dy = smb + buf * 8192;
#pragma unroll
    for (int k = 0; k < 4; k++) cp16(dy + (tid + k * 128) * 16, gy + (size_t)(tid + k * 128) * 16);
    const char* gb = (const char*)g_Bf + (size_t)tile * 4096;
    uint32_t db = smb + 16384 + buf * 4096;
#pragma unroll
    for (int k = 0; k < 2; k++) cp16(db + (tid + k * 128) * 16, gb + (size_t)(tid + k * 128) * 16);
    if (tid < 16) cp16(smb + 24576 + buf * 256 + tid * 16, (const char*)(g_cyn + tile * 64) + tid * 16);
}

__global__ void __launch_bounds__(128, 5)
rbf_main(const float* __restrict__ ls) {
    __shared__ __align__(16) char sm[SMEM_BYTES];
    const uint32_t smb = smem_u32(sm);
    const int tid = threadIdx.x, w = tid >> 5, l = tid & 31;
    const int bidx = blockIdx.x;           // i-block 0..127 (128 rows each)
    const int sl = blockIdx.y;             // j-slice 0..8
    const int tstart = (sl < 4) ? 29 * sl : (116 + 28 * (sl - 4));
    const int tcnt = (sl < 4) ? 29 : 28;
    const int ig = bidx * 128 + w * 32;    // first i-row of this warp's 32

    uint32_t xfA[16], xfB[16];
    {
        const uint4* pA = (const uint4*)(g_Xf + ((size_t)(bidx * 8 + 2 * w) * 32 + l) * 16);
        const uint4* pB = (const uint4*)(g_Xf + ((size_t)(bidx * 8 + 2 * w + 1) * 32 + l) * 16);
#pragma unroll
        for (int q = 0; q < 4; q++) { *(uint4*)(xfA + 4 * q) = pA[q]; *(uint4*)(xfB + 4 * q) = pB[q]; }
    }
    const float cxnA0 = g_cxn[ig + (l >> 2)];
    const float cxnA1 = g_cxn[ig + (l >> 2) + 8];
    const float cxnB0 = g_cxn[ig + (l >> 2) + 16];
    const float cxnB1 = g_cxn[ig + (l >> 2) + 24];
    const float C2 = 2.f * __ldg(ls) * LOG2E;

    float o0A[4] = {0.f, 0.f, 0.f, 0.f}, o1A[4] = {0.f, 0.f, 0.f, 0.f};
    float o0B[4] = {0.f, 0.f, 0.f, 0.f}, o1B[4] = {0.f, 0.f, 0.f, 0.f};

    issue_loads(smb, tstart, 0, tid);
    CP_COMMIT();

    for (int tt = 0; tt < tcnt; tt++) {
        CP_WAIT0();
        __syncthreads();
        if (tt + 1 < tcnt) { issue_loads(smb, tstart + tt + 1, (tt + 1) & 1, tid); CP_COMMIT(); }
        const int buf = tt & 1;
        const char* syb = sm + buf * 8192;
        const char* sbb = sm + 16384 + buf * 4096;
        const char* scy = sm + 24576 + buf * 256;

#pragma unroll
        for (int g = 0; g < 4; g++) {
            uint32_t wahA[4], walA[4], wahB[4], walB[4];
            // ---- load y frags for both h up front (16 regs, dead after burst) ----
            const char* yb0 = syb + (g * 2) * 1024 + l * 32;
            const char* yb1 = syb + (g * 2 + 1) * 1024 + l * 32;
            uint4 y00 = *(const uint4*)yb0;          // h0, Yh|Yl k0..k1 (first 16 j? no: h0 frag pair)
            uint4 y01 = *(const uint4*)(yb0 + 16);
            uint4 y10 = *(const uint4*)yb1;
            uint4 y11 = *(const uint4*)(yb1 + 16);

            // ---- GEMM1 burst: 24 MMAs, 4 chains (sA,sB,tA,tB) round-robin ----
            float sA[4] = {0.f, 0.f, 0.f, 0.f}, sB[4] = {0.f, 0.f, 0.f, 0.f};
            float tA[4] = {0.f, 0.f, 0.f, 0.f}, tB[4] = {0.f, 0.f, 0.f, 0.f};
            mma_bf16(sA, xfA + 0,  y00.x, y00.y);   // h0 Xh·Yh k0
            mma_bf16(sB, xfB + 0,  y00.x, y00.y);
            mma_bf16(tA, xfA + 0,  y10.x, y10.y);   // h1 Xh·Yh k0
            mma_bf16(tB, xfB + 0,  y10.x, y10.y);
            mma_bf16(sA, xfA + 4,  y00.z, y00.w);   // h0 Xh·Yh k1
            mma_bf16(sB, xfB + 4,  y00.z, y00.w);
            mma_bf16(tA, xfA + 4,  y10.z, y10.w);
            mma_bf16(tB, xfB + 4,  y10.z, y10.w);
            mma_bf16(sA, xfA + 0,  y01.x, y01.y);   // h0 Xh·Yl k0
            mma_bf16(sB, xfB + 0,  y01.x, y01.y);
            mma_bf16(tA, xfA + 0,  y11.x, y11.y);
            mma_bf16(tB, xfB + 0,  y11.x, y11.y);
            mma_bf16(sA, xfA + 4,  y01.z, y01.w);   // h0 Xh·Yl k1
            mma_bf16(sB, xfB + 4,  y01.z, y01.w);
            mma_bf16(tA, xfA + 4,  y11.z, y11.w);
            mma_bf16(tB, xfB + 4,  y11.z, y11.w);
            mma_bf16(sA, xfA + 8,  y00.x, y00.y);   // h0 Xl·Yh k0
            mma_bf16(sB, xfB + 8,  y00.x, y00.y);
            mma_bf16(tA, xfA + 8,  y10.x, y10.y);
            mma_bf16(tB, xfB + 8,  y10.x, y10.y);
            mma_bf16(sA, xfA + 12, y00.z, y00.w);   // h0 Xl·Yh k1
            mma_bf16(sB, xfB + 12, y00.z, y00.w);
            mma_bf16(tA, xfA + 12, y10.z, y10.w);
            mma_bf16(tB, xfB + 12, y10.z, y10.w);

            // ---- epilogue h0 ----
            {
                float2 cy = *(const float2*)(scy + (g * 2) * 32 + (l & 3) * 8);
                float w0 = ex2f(fminf(fmaf(C2, sA[0], cxnA0 + cy.x), 0.f));
                float w1 = ex2f(fminf(fmaf(C2, sA[1], cxnA0 + cy.y), 0.f));
                float w2 = ex2f(fminf(fmaf(C2, sA[2], cxnA1 + cy.x), 0.f));
                float w3 = ex2f(fminf(fmaf(C2, sA[3], cxnA1 + cy.y), 0.f));
                uint32_t h01 = pk2(w0, w1), h23 = pk2(w2, w3);
                wahA[0] = h01; wahA[1] = h23;
                walA[0] = pk2(w0 - bflo(h01), w1 - bfhi(h01));
                walA[1] = pk2(w2 - bflo(h23), w3 - bfhi(h23));
                float v0 = ex2f(fminf(fmaf(C2, sB[0], cxnB0 + cy.x), 0.f));
                float v1 = ex2f(fminf(fmaf(C2, sB[1], cxnB0 + cy.y), 0.f));
                float v2 = ex2f(fminf(fmaf(C2, sB[2], cxnB1 + cy.x), 0.f));
                float v3 = ex2f(fminf(fmaf(C2, sB[3], cxnB1 + cy.y), 0.f));
                uint32_t g01 = pk2(v0, v1), g23 = pk2(v2, v3);
                wahB[0] = g01; wahB[1] = g23;
                walB[0] = pk2(v0 - bflo(g01), v1 - bfhi(g01));
                walB[1] = pk2(v2 - bflo(g23), v3 - bfhi(g23));
            }
            // ---- epilogue h1 ----
            {
                float2 cy = *(const float2*)(scy + (g * 2 + 1) * 32 + (l & 3) * 8);
                float w0 = ex2f(fminf(fmaf(C2, tA[0], cxnA0 + cy.x), 0.f));
                float w1 = ex2f(fminf(fmaf(C2, tA[1], cxnA0 + cy.y), 0.f));
                float w2 = ex2f(fminf(fmaf(C2, tA[2], cxnA1 + cy.x), 0.f));
                float w3 = ex2f(fminf(fmaf(C2, tA[3], cxnA1 + cy.y), 0.f));
                uint32_t h01 = pk2(w0, w1), h23 = pk2(w2, w3);
                wahA[2] = h01; wahA[3] = h23;
                walA[2] = pk2(w0 - bflo(h01), w1 - bfhi(h01));
                walA[3] = pk2(w2 - bflo(h23), w3 - bfhi(h23));
                float v0 = ex2f(fminf(fmaf(C2, tB[0], cxnB0 + cy.x), 0.f));
                float v1 = ex2f(fminf(fmaf(C2, tB[1], cxnB0 + cy.y), 0.f));
                float v2 = ex2f(fminf(fmaf(C2, tB[2], cxnB1 + cy.x), 0.f));
                float v3 = ex2f(fminf(fmaf(C2, tB[3], cxnB1 + cy.y), 0.f));
                uint32_t g01 = pk2(v0, v1), g23 = pk2(v2, v3);
                wahB[2] = g01; wahB[3] = g23;
                walB[2] = pk2(v0 - bflo(g01), v1 - bfhi(g01));
                walB[3] = pk2(v2 - bflo(g23), v3 - bfhi(g23));
            }
            // ---- GEMM2: 4 accumulator chains round-robin ----
            uint4 b0 = *(const uint4*)(sbb + (g * 2) * 512 + l * 16);
            uint4 b1 = *(const uint4*)(sbb + (g * 2 + 1) * 512 + l * 16);
            mma_bf16(o0A, wahA, b0.x, b0.y);
            mma_bf16(o0B, wahB, b0.x, b0.y);
            mma_bf16(o1A, wahA, b1.x, b1.y);
            mma_bf16(o1B, wahB, b1.x, b1.y);
            mma_bf16(o0A, wahA, b0.z, b0.w);
            mma_bf16(o0B, wahB, b0.z, b0.w);
            mma_bf16(o1A, wahA, b1.z, b1.w);
            mma_bf16(o1B, wahB, b1.z, b1.w);
            mma_bf16(o0A, walA, b0.x, b0.y);
            mma_bf16(o0B, walB, b0.x, b0.y);
            mma_bf16(o1A, walA, b1.x, b1.y);
            mma_bf16(o1B, walB, b1.x, b1.y);
        }
    }

    // partial write: slice-local buffer
    float* op = g_Op + (size_t)sl * (NP * 16);
    const int cb = 2 * (l & 3);
    const int rA = ig + (l >> 2), rB = rA + 16;
    *(float2*)(op + (size_t)rA * 16 + cb)            = make_float2(o0A[0], o0A[1]);
    *(float2*)(op + (size_t)rA * 16 + 8 + cb)        = make_float2(o1A[0], o1A[1]);
    *(float2*)(op + (size_t)(rA + 8) * 16 + cb)      = make_float2(o0A[2], o0A[3]);
    *(float2*)(op + (size_t)(rA + 8) * 16 + 8 + cb)  = make_float2(o1A[2], o1A[3]);
    *(float2*)(op + (size_t)rB * 16 + cb)            = make_float2(o0B[0], o0B[1]);
    *(float2*)(op + (size_t)rB * 16 + 8 + cb)        = make_float2(o1B[0], o1B[1]);
    *(float2*)(op + (size_t)(rB + 8) * 16 + cb)      = make_float2(o0B[2], o0B[3]);
    *(float2*)(op + (size_t)(rB + 8) * 16 + 8 + cb)  = make_float2(o1B[2], o1B[3]);
}

// ================= deterministic slice reduction =================
__global__ void reduce_k(float* __restrict__ out) {
    int idx = blockIdx.x * 256 + threadIdx.x;
    float4 o = ((const float4*)g_Op)[idx];
#pragma unroll
    for (int s = 1; s < NSL; s++) {
        float4 v = ((const float4*)(g_Op + (size_t)s * NP * 16))[idx];
        o.x += v.x; o.y += v.y; o.z += v.z; o.w += v.w;   // fixed slice order
    }
    ((float4*)out)[idx] = o;
}

extern "C" void kernel_launch(void* const* d_in, const int* in_sizes, int n_in,
                              void* d_out, int out_size) {
    const float* ls = (const float*)d_in[0];
    const float* x  = (const float*)d_in[1];
    const float* y  = (const float*)d_in[2];
    const float* b  = (const float*)d_in[3];
    float* out = (float*)d_out;

    prep_x<<<256, 128>>>(ls, x);
    prep_y<<<512, 128>>>(ls, y);
    prep_b<<<512, 128>>>(b);
    rbf_main<<<dim3(128, NSL), 128>>>(ls);
    reduce_k<<<256, 256>>>(out);
}

// round 14
// speedup vs baseline: 1.0609x; 1.0292x over previous
#include <cuda_runtime.h>
#include <cuda_bf16.h>
#include <cstdint>

#define LOG2E 1.4426950408889634f
#define NP  16384
#define NT  256      // j-tiles of 64
#define NWG 1024     // i row-groups of 16
#define NSL 18       // j-slices: 4x15 + 14x14 = 256

// ---- static device scratch (no allocation) ----
__device__ uint32_t g_Xf[NWG * 32 * 16];  // a-frag image
__device__ uint32_t g_Yf[NT * 2048];      // b-frag image (GEMM1)
__device__ uint32_t g_Bf[NT * 1024];      // b-frag image (GEMM2)
__device__ float g_cxn[NP];
__device__ float g_cyn[NP];
__device__ float g_Op[NSL * NP * 16];     // per-slice fp32 partials (18 MB)

// ---- helpers ----
__device__ __forceinline__ uint32_t smem_u32(const void* p) {
    uint32_t a;
    asm("{ .reg .u64 t; cvta.to.shared.u64 t, %1; cvt.u32.u64 %0, t; }" : "=r"(a) : "l"(p));
    return a;
}
__device__ __forceinline__ void cp16(uint32_t d, const void* s) {
    asm volatile("cp.async.cg.shared.global [%0], [%1], 16;" :: "r"(d), "l"(s));
}
#define CP_COMMIT() asm volatile("cp.async.commit_group;" ::: "memory")
#define CP_WAIT0()  asm volatile("cp.async.wait_group 0;" ::: "memory")

__device__ __forceinline__ void mma_bf16(float* d, const uint32_t* a, uint32_t b0, uint32_t b1) {
    asm volatile("mma.sync.aligned.m16n8k16.row.col.f32.bf16.bf16.f32 "
                 "{%0,%1,%2,%3},{%4,%5,%6,%7},{%8,%9},{%0,%1,%2,%3};"
                 : "+f"(d[0]), "+f"(d[1]), "+f"(d[2]), "+f"(d[3])
                 : "r"(a[0]), "r"(a[1]), "r"(a[2]), "r"(a[3]), "r"(b0), "r"(b1));
}
__device__ __forceinline__ float ex2f(float a) {
    float r; asm("ex2.approx.ftz.f32 %0, %1;" : "=f"(r) : "f"(a)); return r;
}
__device__ __forceinline__ uint32_t pk2(float lo, float hi) {
    __nv_bfloat162 h = __float22bfloat162_rn(make_float2(lo, hi));
    return *(uint32_t*)&h;
}
__device__ __forceinline__ float bflo(uint32_t u) { return __uint_as_float(u << 16); }
__device__ __forceinline__ float bfhi(uint32_t u) { return __uint_as_float(u & 0xffff0000u); }
__device__ __forceinline__ uint32_t pk_split(float a, float b, int low) {
    float ah = __bfloat162float(__float2bfloat16(a));
    float bh = __bfloat162float(__float2bfloat16(b));
    return low ? pk2(a - ah, b - bh) : pk2(ah, bh);
}

// ================= fused prep kernel =================
// 512 blocks x 128 threads = 65536 threads.
// t < 32768 : prep X (wg = t>>5)
// all t     : prep Y (tn = t>>5) and prep B
__global__ void prep_all(const float* __restrict__ ls, const float* __restrict__ x,
                         const float* __restrict__ y, const float* __restrict__ b) {
    int t = blockIdx.x * 128 + threadIdx.x;
    int l = t & 31;
    const float cneg = -ls[0] * LOG2E;

    // ---- X a-frags (threads 0..32767) ----
    if (t < 32768) {
        int wg = t >> 5;
        int r0 = wg * 16 + (l >> 2), r1 = r0 + 8;
        int c = 2 * (l & 3);
        const float* x0 = x + (size_t)r0 * 32;
        const float* x1 = x + (size_t)r1 * 32;
        float v0[8], v1[8], n0 = 0.f, n1 = 0.f;
#pragma unroll
        for (int kf = 0; kf < 2; kf++)
#pragma unroll
            for (int h = 0; h < 2; h++)
#pragma unroll
                for (int e = 0; e < 2; e++) {
                    int idx = kf * 4 + h * 2 + e;
                    int col = kf * 16 + h * 8 + c + e;
                    v0[idx] = x0[col]; v1[idx] = x1[col];
                    n0 += v0[idx] * v0[idx];
                    n1 += v1[idx] * v1[idx];
                }
        n0 += __shfl_xor_sync(0xffffffffu, n0, 1); n0 += __shfl_xor_sync(0xffffffffu, n0, 2);
        n1 += __shfl_xor_sync(0xffffffffu, n1, 1); n1 += __shfl_xor_sync(0xffffffffu, n1, 2);
        if ((l & 3) == 0) { g_cxn[r0] = cneg * n0; g_cxn[r1] = cneg * n1; }

        uint32_t o[16];
#pragma unroll
        for (int s = 0; s < 2; s++)
#pragma unroll
            for (int kf = 0; kf < 2; kf++)
#pragma unroll
                for (int h = 0; h < 2; h++) {
                    o[s * 8 + kf * 4 + h * 2 + 0] = pk_split(v0[kf * 4 + h * 2], v0[kf * 4 + h * 2 + 1], s);
                    o[s * 8 + kf * 4 + h * 2 + 1] = pk_split(v1[kf * 4 + h * 2], v1[kf * 4 + h * 2 + 1], s);
                }
        uint4* dst = (uint4*)(g_Xf + (size_t)t * 16);
#pragma unroll
        for (int q = 0; q < 4; q++)
            dst[q] = make_uint4(o[4 * q], o[4 * q + 1], o[4 * q + 2], o[4 * q + 3]);
    }

    // ---- Y b-frags (all threads) ----
    {
        int tn = t >> 5;
        int j = tn * 8 + (l >> 2);
        int c = 2 * (l & 3);
        const float* yr = y + (size_t)j * 32;
        float v[8], n = 0.f;
#pragma unroll
        for (int kf = 0; kf < 2; kf++)
#pragma unroll
            for (int h = 0; h < 2; h++)
#pragma unroll
                for (int e = 0; e < 2; e++) {
                    int idx = kf * 4 + h * 2 + e;
                    v[idx] = yr[kf * 16 + h * 8 + c + e];
                    n += v[idx] * v[idx];
                }
        n += __shfl_xor_sync(0xffffffffu, n, 1); n += __shfl_xor_sync(0xffffffffu, n, 2);
        if ((l & 3) == 0) g_cyn[j] = cneg * n;

        uint32_t o[8];
#pragma unroll
        for (int s = 0; s < 2; s++)
#pragma unroll
            for (int kf = 0; kf < 2; kf++)
#pragma unroll
                for (int h = 0; h < 2; h++)
                    o[s * 4 + kf * 2 + h] = pk_split(v[kf * 4 + h * 2], v[kf * 4 + h * 2 + 1], s);
        uint4* dst = (uint4*)(g_Yf + (size_t)tn * 256 + l * 8);
        dst[0] = make_uint4(o[0], o[1], o[2], o[3]);
        dst[1] = make_uint4(o[4], o[5], o[6], o[7]);
    }

    // ---- B b-frags (all threads) ----
    {
        int u = t >> 5;
        int tile = u >> 3, fp = u & 7, kf = fp >> 1, nb2 = fp & 1;
        int c = nb2 * 8 + (l >> 2);
        int jb = tile * 64 + kf * 16 + 2 * (l & 3);
        float p0 = b[(size_t)jb * 16 + c];
        float p1 = b[(size_t)(jb + 1) * 16 + c];
        float p2 = b[(size_t)(jb + 8) * 16 + c];
        float p3 = b[(size_t)(jb + 9) * 16 + c];
        uint32_t h0 = pk_split(p0, p1, 0), h1 = pk_split(p2, p3, 0);
        uint32_t l0 = pk_split(p0, p1, 1), l1 = pk_split(p2, p3, 1);
        *(uint4*)(g_Bf + (size_t)tile * 1024 + fp * 128 + l * 4) = make_uint4(h0, h1, l0, l1);
    }
}

// ================= main kernel: 4 warps x 32 i-rows = 128 i-rows/CTA, 5 CTAs/SM =================
#define SMEM_BYTES 25088

__device__ __forceinline__ void issue_loads(uint32_t smb, int tile, int buf, int tid) {
    const char* gy = (const char*)g_Yf + (size_t)tile * 8192;
    uint32_t dy = smb + buf * 8192;
#pragma unroll
    for (int k = 0; k < 4; k++) cp16(dy + (tid + k * 128) * 16, gy + (size_t)(tid + k * 128) * 16);
    const char* gb = (const char*)g_Bf + (size_t)tile * 4096;
    uint32_t db = smb + 16384 + buf * 4096;
#pragma unroll
    for (int k = 0; k < 2; k++) cp16(db + (tid + k * 128) * 16, gb + (size_t)(tid + k * 128) * 16);
    if (tid < 16) cp16(smb + 24576 + buf * 256 + tid * 16, (const char*)(g_cyn + tile * 64) + tid * 16);
}

__global__ void __launch_bounds__(128, 5)
rbf_main(const float* __restrict__ ls) {
    __shared__ __align__(16) char sm[SMEM_BYTES];
    const uint32_t smb = smem_u32(sm);
    const int tid = threadIdx.x, w = tid >> 5, l = tid & 31;
    const int bidx = blockIdx.x;           // i-block 0..127 (128 rows each)
    const int sl = blockIdx.y;             // j-slice 0..17
    const int tstart = (sl < 4) ? 15 * sl : (60 + 14 * (sl - 4));
    const int tcnt = (sl < 4) ? 15 : 14;
    const int ig = bidx * 128 + w * 32;    // first i-row of this warp's 32

    uint32_t xfA[16], xfB[16];
    {
        const uint4* pA = (const uint4*)(g_Xf + ((size_t)(bidx * 8 + 2 * w) * 32 + l) * 16);
        const uint4* pB = (const uint4*)(g_Xf + ((size_t)(bidx * 8 + 2 * w + 1) * 32 + l) * 16);
#pragma unroll
        for (int q = 0; q < 4; q++) { *(uint4*)(xfA + 4 * q) = pA[q]; *(uint4*)(xfB + 4 * q) = pB[q]; }
    }
    const float cxnA0 = g_cxn[ig + (l >> 2)];
    const float cxnA1 = g_cxn[ig + (l >> 2) + 8];
    const float cxnB0 = g_cxn[ig + (l >> 2) + 16];
    const float cxnB1 = g_cxn[ig + (l >> 2) + 24];
    const float C2 = 2.f * __ldg(ls) * LOG2E;

    float o0A[4] = {0.f, 0.f, 0.f, 0.f}, o1A[4] = {0.f, 0.f, 0.f, 0.f};
    float o0B[4] = {0.f, 0.f, 0.f, 0.f}, o1B[4] = {0.f, 0.f, 0.f, 0.f};

    issue_loads(smb, tstart, 0, tid);
    CP_COMMIT();

    for (int tt = 0; tt < tcnt; tt++) {
        CP_WAIT0();
        __syncthreads();
        if (tt + 1 < tcnt) { issue_loads(smb, tstart + tt + 1, (tt + 1) & 1, tid); CP_COMMIT(); }
        const int buf = tt & 1;
        const char* syb = sm + buf * 8192;
        const char* sbb = sm + 16384 + buf * 4096;
        const char* scy = sm + 24576 + buf * 256;

#pragma unroll
        for (int g = 0; g < 4; g++) {
            uint32_t wahA[4], walA[4], wahB[4], walB[4];
            const char* yb0 = syb + (g * 2) * 1024 + l * 32;
            const char* yb1 = syb + (g * 2 + 1) * 1024 + l * 32;
            uint4 y00 = *(const uint4*)yb0;
            uint4 y01 = *(const uint4*)(yb0 + 16);
            uint4 y10 = *(const uint4*)yb1;
            uint4 y11 = *(const uint4*)(yb1 + 16);

            // ---- GEMM1 burst: 24 MMAs, 4 chains (sA,sB,tA,tB) round-robin ----
            float sA[4] = {0.f, 0.f, 0.f, 0.f}, sB[4] = {0.f, 0.f, 0.f, 0.f};
            float tA[4] = {0.f, 0.f, 0.f, 0.f}, tB[4] = {0.f, 0.f, 0.f, 0.f};
            mma_bf16(sA, xfA + 0,  y00.x, y00.y);
            mma_bf16(sB, xfB + 0,  y00.x, y00.y);
            mma_bf16(tA, xfA + 0,  y10.x, y10.y);
            mma_bf16(tB, xfB + 0,  y10.x, y10.y);
            mma_bf16(sA, xfA + 4,  y00.z, y00.w);
            mma_bf16(sB, xfB + 4,  y00.z, y00.w);
            mma_bf16(tA, xfA + 4,  y10.z, y10.w);
            mma_bf16(tB, xfB + 4,  y10.z, y10.w);
            mma_bf16(sA, xfA + 0,  y01.x, y01.y);
            mma_bf16(sB, xfB + 0,  y01.x, y01.y);
            mma_bf16(tA, xfA + 0,  y11.x, y11.y);
            mma_bf16(tB, xfB + 0,  y11.x, y11.y);
            mma_bf16(sA, xfA + 4,  y01.z, y01.w);
            mma_bf16(sB, xfB + 4,  y01.z, y01.w);
            mma_bf16(tA, xfA + 4,  y11.z, y11.w);
            mma_bf16(tB, xfB + 4,  y11.z, y11.w);
            mma_bf16(sA, xfA + 8,  y00.x, y00.y);
            mma_bf16(sB, xfB + 8,  y00.x, y00.y);
            mma_bf16(tA, xfA + 8,  y10.x, y10.y);
            mma_bf16(tB, xfB + 8,  y10.x, y10.y);
            mma_bf16(sA, xfA + 12, y00.z, y00.w);
            mma_bf16(sB, xfB + 12, y00.z, y00.w);
            mma_bf16(tA, xfA + 12, y10.z, y10.w);
            mma_bf16(tB, xfB + 12, y10.z, y10.w);

            // ---- epilogue h0 ----
            {
                float2 cy = *(const float2*)(scy + (g * 2) * 32 + (l & 3) * 8);
                float w0 = ex2f(fminf(fmaf(C2, sA[0], cxnA0 + cy.x), 0.f));
                float w1 = ex2f(fminf(fmaf(C2, sA[1], cxnA0 + cy.y), 0.f));
                float w2 = ex2f(fminf(fmaf(C2, sA[2], cxnA1 + cy.x), 0.f));
                float w3 = ex2f(fminf(fmaf(C2, sA[3], cxnA1 + cy.y), 0.f));
                uint32_t h01 = pk2(w0, w1), h23 = pk2(w2, w3);
                wahA[0] = h01; wahA[1] = h23;
                walA[0] = pk2(w0 - bflo(h01), w1 - bfhi(h01));
                walA[1] = pk2(w2 - bflo(h23), w3 - bfhi(h23));
                float v0 = ex2f(fminf(fmaf(C2, sB[0], cxnB0 + cy.x), 0.f));
                float v1 = ex2f(fminf(fmaf(C2, sB[1], cxnB0 + cy.y), 0.f));
                float v2 = ex2f(fminf(fmaf(C2, sB[2], cxnB1 + cy.x), 0.f));
                float v3 = ex2f(fminf(fmaf(C2, sB[3], cxnB1 + cy.y), 0.f));
                uint32_t g01 = pk2(v0, v1), g23 = pk2(v2, v3);
                wahB[0] = g01; wahB[1] = g23;
                walB[0] = pk2(v0 - bflo(g01), v1 - bfhi(g01));
                walB[1] = pk2(v2 - bflo(g23), v3 - bfhi(g23));
            }
            // ---- epilogue h1 ----
            {
                float2 cy = *(const float2*)(scy + (g * 2 + 1) * 32 + (l & 3) * 8);
                float w0 = ex2f(fminf(fmaf(C2, tA[0], cxnA0 + cy.x), 0.f));
                float w1 = ex2f(fminf(fmaf(C2, tA[1], cxnA0 + cy.y), 0.f));
                float w2 = ex2f(fminf(fmaf(C2, tA[2], cxnA1 + cy.x), 0.f));
                float w3 = ex2f(fminf(fmaf(C2, tA[3], cxnA1 + cy.y), 0.f));
                uint32_t h01 = pk2(w0, w1), h23 = pk2(w2, w3);
                wahA[2] = h01; wahA[3] = h23;
                walA[2] = pk2(w0 - bflo(h01), w1 - bfhi(h01));
                walA[3] = pk2(w2 - bflo(h23), w3 - bfhi(h23));
                float v0 = ex2f(fminf(fmaf(C2, tB[0], cxnB0 + cy.x), 0.f));
                float v1 = ex2f(fminf(fmaf(C2, tB[1], cxnB0 + cy.y), 0.f));
                float v2 = ex2f(fminf(fmaf(C2, tB[2], cxnB1 + cy.x), 0.f));
                float v3 = ex2f(fminf(fmaf(C2, tB[3], cxnB1 + cy.y), 0.f));
                uint32_t g01 = pk2(v0, v1), g23 = pk2(v2, v3);
                wahB[2] = g01; wahB[3] = g23;
                walB[2] = pk2(v0 - bflo(g01), v1 - bfhi(g01));
                walB[3] = pk2(v2 - bflo(g23), v3 - bfhi(g23));
            }
            // ---- GEMM2: 4 accumulator chains round-robin ----
            uint4 b0 = *(const uint4*)(sbb + (g * 2) * 512 + l * 16);
            uint4 b1 = *(const uint4*)(sbb + (g * 2 + 1) * 512 + l * 16);
            mma_bf16(o0A, wahA, b0.x, b0.y);
            mma_bf16(o0B, wahB, b0.x, b0.y);
            mma_bf16(o1A, wahA, b1.x, b1.y);
            mma_bf16(o1B, wahB, b1.x, b1.y);
            mma_bf16(o0A, wahA, b0.z, b0.w);
            mma_bf16(o0B, wahB, b0.z, b0.w);
            mma_bf16(o1A, wahA, b1.z, b1.w);
            mma_bf16(o1B, wahB, b1.z, b1.w);
            mma_bf16(o0A, walA, b0.x, b0.y);
            mma_bf16(o0B, walB, b0.x, b0.y);
            mma_bf16(o1A, walA, b1.x, b1.y);
            mma_bf16(o1B, walB, b1.x, b1.y);
        }
    }

    // partial write: slice-local buffer
    float* op = g_Op + (size_t)sl * (NP * 16);
    const int cb = 2 * (l & 3);
    const int rA = ig + (l >> 2), rB = rA + 16;
    *(float2*)(op + (size_t)rA * 16 + cb)            = make_float2(o0A[0], o0A[1]);
    *(float2*)(op + (size_t)rA * 16 + 8 + cb)        = make_float2(o1A[0], o1A[1]);
    *(float2*)(op + (size_t)(rA + 8) * 16 + cb)      = make_float2(o0A[2], o0A[3]);
    *(float2*)(op + (size_t)(rA + 8) * 16 + 8 + cb)  = make_float2(o1A[2], o1A[3]);
    *(float2*)(op + (size_t)rB * 16 + cb)            = make_float2(o0B[0], o0B[1]);
    *(float2*)(op + (size_t)rB * 16 + 8 + cb)        = make_float2(o1B[0], o1B[1]);
    *(float2*)(op + (size_t)(rB + 8) * 16 + cb)      = make_float2(o0B[2], o0B[3]);
    *(float2*)(op + (size_t)(rB + 8) * 16 + 8 + cb)  = make_float2(o1B[2], o1B[3]);
}

// ================= deterministic slice reduction =================
__global__ void reduce_k(float* __restrict__ out) {
    int idx = blockIdx.x * 256 + threadIdx.x;
    float4 o = ((const float4*)g_Op)[idx];
#pragma unroll
    for (int s = 1; s < NSL; s++) {
        float4 v = ((const float4*)(g_Op + (size_t)s * NP * 16))[idx];
        o.x += v.x; o.y += v.y; o.z += v.z; o.w += v.w;   // fixed slice order
    }
    ((float4*)out)[idx] = o;
}

extern "C" void kernel_launch(void* const* d_in, const int* in_sizes, int n_in,
                              void* d_out, int out_size) {
    const float* ls = (const float*)d_in[0];
    const float* x  = (const float*)d_in[1];
    const float* y  = (const float*)d_in[2];
    const float* b  = (const float*)d_in[3];
    float* out = (float*)d_out;

    prep_all<<<512, 128>>>(ls, x, y, b);
    rbf_main<<<dim3(128, NSL), 128>>>(ls);
    reduce_k<<<256, 256>>>(out);
}

// round 15
// speedup vs baseline: 1.0612x; 1.0003x over previous
#include <cuda_runtime.h>
#include <cuda_bf16.h>
#include <cstdint>

#define LOG2E 1.4426950408889634f
#define NP  16384
#define NT  256      // j-tiles of 64
#define NWG 1024     // i row-groups of 16
#define NSL 18       // j-slices: 4x15 + 14x14 = 256

// ---- static device scratch (no allocation) ----
__device__ uint32_t g_Xf[NWG * 32 * 16];  // a-frag image
__device__ uint32_t g_Yf[NT * 2048];      // b-frag image (GEMM1)
__device__ uint32_t g_Bf[NT * 1024];      // b-frag image (GEMM2)
__device__ float g_cxn[NP];
__device__ float g_cyn[NP];
__device__ float g_Op[NSL * NP * 16];     // per-slice fp32 partials (18 MB)

// ---- helpers ----
__device__ __forceinline__ uint32_t smem_u32(const void* p) {
    uint32_t a;
    asm("{ .reg .u64 t; cvta.to.shared.u64 t, %1; cvt.u32.u64 %0, t; }" : "=r"(a) : "l"(p));
    return a;
}
__device__ __forceinline__ void cp16(uint32_t d, const void* s) {
    asm volatile("cp.async.cg.shared.global [%0], [%1], 16;" :: "r"(d), "l"(s));
}
#define CP_COMMIT() asm volatile("cp.async.commit_group;" ::: "memory")
#define CP_WAIT0()  asm volatile("cp.async.wait_group 0;" ::: "memory")

__device__ __forceinline__ void mma_bf16(float* d, const uint32_t* a, uint32_t b0, uint32_t b1) {
    asm volatile("mma.sync.aligned.m16n8k16.row.col.f32.bf16.bf16.f32 "
                 "{%0,%1,%2,%3},{%4,%5,%6,%7},{%8,%9},{%0,%1,%2,%3};"
                 : "+f"(d[0]), "+f"(d[1]), "+f"(d[2]), "+f"(d[3])
                 : "r"(a[0]), "r"(a[1]), "r"(a[2]), "r"(a[3]), "r"(b0), "r"(b1));
}
__device__ __forceinline__ float ex2f(float a) {
    float r; asm("ex2.approx.ftz.f32 %0, %1;" : "=f"(r) : "f"(a)); return r;
}
__device__ __forceinline__ uint32_t pk2(float lo, float hi) {
    __nv_bfloat162 h = __float22bfloat162_rn(make_float2(lo, hi));
    return *(uint32_t*)&h;
}
__device__ __forceinline__ float bflo(uint32_t u) { return __uint_as_float(u << 16); }
__device__ __forceinline__ float bfhi(uint32_t u) { return __uint_as_float(u & 0xffff0000u); }
__device__ __forceinline__ uint32_t pk_split(float a, float b, int low) {
    float ah = __bfloat162float(__float2bfloat16(a));
    float bh = __bfloat162float(__float2bfloat16(b));
    return low ? pk2(a - ah, b - bh) : pk2(ah, bh);
}

// ================= fused prep kernel: ONE task per thread =================
// grid 1280 x 128 = 163840 threads:
//   u in [0, 32768)        : X a-frag task  (wg = u>>5)
//   u in [32768, 98304)    : Y b-frag task  (tn = (u-32768)>>5)
//   u in [98304, 163840)   : B b-frag task
// All boundaries are warp-aligned, so intra-task shfl reductions stay valid.
__global__ void prep_all(const float* __restrict__ ls, const float* __restrict__ x,
                         const float* __restrict__ y, const float* __restrict__ b) {
    int u = blockIdx.x * 128 + threadIdx.x;
    int l = u & 31;
    const float cneg = -ls[0] * LOG2E;

    if (u < 32768) {
        // ---- X a-frags ----
        int t = u;
        int wg = t >> 5;
        int r0 = wg * 16 + (l >> 2), r1 = r0 + 8;
        int c = 2 * (l & 3);
        const float* x0 = x + (size_t)r0 * 32;
        const float* x1 = x + (size_t)r1 * 32;
        float v0[8], v1[8], n0 = 0.f, n1 = 0.f;
#pragma unroll
        for (int kf = 0; kf < 2; kf++)
#pragma unroll
            for (int h = 0; h < 2; h++)
#pragma unroll
                for (int e = 0; e < 2; e++) {
                    int idx = kf * 4 + h * 2 + e;
                    int col = kf * 16 + h * 8 + c + e;
                    v0[idx] = x0[col]; v1[idx] = x1[col];
                    n0 += v0[idx] * v0[idx];
                    n1 += v1[idx] * v1[idx];
                }
        n0 += __shfl_xor_sync(0xffffffffu, n0, 1); n0 += __shfl_xor_sync(0xffffffffu, n0, 2);
        n1 += __shfl_xor_sync(0xffffffffu, n1, 1); n1 += __shfl_xor_sync(0xffffffffu, n1, 2);
        if ((l & 3) == 0) { g_cxn[r0] = cneg * n0; g_cxn[r1] = cneg * n1; }

        uint32_t o[16];
#pragma unroll
        for (int s = 0; s < 2; s++)
#pragma unroll
            for (int kf = 0; kf < 2; kf++)
#pragma unroll
                for (int h = 0; h < 2; h++) {
                    o[s * 8 + kf * 4 + h * 2 + 0] = pk_split(v0[kf * 4 + h * 2], v0[kf * 4 + h * 2 + 1], s);
                    o[s * 8 + kf * 4 + h * 2 + 1] = pk_split(v1[kf * 4 + h * 2], v1[kf * 4 + h * 2 + 1], s);
                }
        uint4* dst = (uint4*)(g_Xf + (size_t)t * 16);
#pragma unroll
        for (int q = 0; q < 4; q++)
            dst[q] = make_uint4(o[4 * q], o[4 * q + 1], o[4 * q + 2], o[4 * q + 3]);
    } else if (u < 98304) {
        // ---- Y b-frags ----
        int t = u - 32768;
        int tn = t >> 5;
        int j = tn * 8 + (l >> 2);
        int c = 2 * (l & 3);
        const float* yr = y + (size_t)j * 32;
        float v[8], n = 0.f;
#pragma unroll
        for (int kf = 0; kf < 2; kf++)
#pragma unroll
            for (int h = 0; h < 2; h++)
#pragma unroll
                for (int e = 0; e < 2; e++) {
                    int idx = kf * 4 + h * 2 + e;
                    v[idx] = yr[kf * 16 + h * 8 + c + e];
                    n += v[idx] * v[idx];
                }
        n += __shfl_xor_sync(0xffffffffu, n, 1); n += __shfl_xor_sync(0xffffffffu, n, 2);
        if ((l & 3) == 0) g_cyn[j] = cneg * n;

        uint32_t o[8];
#pragma unroll
        for (int s = 0; s < 2; s++)
#pragma unroll
            for (int kf = 0; kf < 2; kf++)
#pragma unroll
                for (int h = 0; h < 2; h++)
                    o[s * 4 + kf * 2 + h] = pk_split(v[kf * 4 + h * 2], v[kf * 4 + h * 2 + 1], s);
        uint4* dst = (uint4*)(g_Yf + (size_t)tn * 256 + l * 8);
        dst[0] = make_uint4(o[0], o[1], o[2], o[3]);
        dst[1] = make_uint4(o[4], o[5], o[6], o[7]);
    } else {
        // ---- B b-frags ----
        int t = u - 98304;
        int uu = t >> 5;
        int tile = uu >> 3, fp = uu & 7, kf = fp >> 1, nb2 = fp & 1;
        int c = nb2 * 8 + (l >> 2);
        int jb = tile * 64 + kf * 16 + 2 * (l & 3);
        float p0 = b[(size_t)jb * 16 + c];
        float p1 = b[(size_t)(jb + 1) * 16 + c];
        float p2 = b[(size_t)(jb + 8) * 16 + c];
        float p3 = b[(size_t)(jb + 9) * 16 + c];
        uint32_t h0 = pk_split(p0, p1, 0), h1 = pk_split(p2, p3, 0);
        uint32_t l0 = pk_split(p0, p1, 1), l1 = pk_split(p2, p3, 1);
        *(uint4*)(g_Bf + (size_t)tile * 1024 + fp * 128 + l * 4) = make_uint4(h0, h1, l0, l1);
    }
}

// ================= main kernel: 4 warps x 32 i-rows = 128 i-rows/CTA, 5 CTAs/SM =================
#define SMEM_BYTES 25088

__device__ __forceinline__ void issue_loads(uint32_t smb, int tile, int buf, int tid) {
    const char* gy = (const char*)g_Yf + (size_t)tile * 8192;
    uint32_t dy = smb + buf * 8192;
#pragma unroll
    for (int k = 0; k < 4; k++) cp16(dy + (tid + k * 128) * 16, gy + (size_t)(tid + k * 128) * 16);
    const char* gb = (const char*)g_Bf + (size_t)tile * 4096;
    uint32_t db = smb + 16384 + buf * 4096;
#pragma unroll
    for (int k = 0; k < 2; k++) cp16(db + (tid + k * 128) * 16, gb + (size_t)(tid + k * 128) * 16);
    if (tid < 16) cp16(smb + 24576 + buf * 256 + tid * 16, (const char*)(g_cyn + tile * 64) + tid * 16);
}

__global__ void __launch_bounds__(128, 5)
rbf_main(const float* __restrict__ ls) {
    __shared__ __align__(16) char sm[SMEM_BYTES];
    const uint32_t smb = smem_u32(sm);
    const int tid = threadIdx.x, w = tid >> 5, l = tid & 31;
    const int bidx = blockIdx.x;           // i-block 0..127 (128 rows each)
    const int sl = blockIdx.y;             // j-slice 0..17
    const int tstart = (sl < 4) ? 15 * sl : (60 + 14 * (sl - 4));
    const int tcnt = (sl < 4) ? 15 : 14;
    const int ig = bidx * 128 + w * 32;    // first i-row of this warp's 32

    uint32_t xfA[16], xfB[16];
    {
        const uint4* pA = (const uint4*)(g_Xf + ((size_t)(bidx * 8 + 2 * w) * 32 + l) * 16);
        const uint4* pB = (const uint4*)(g_Xf + ((size_t)(bidx * 8 + 2 * w + 1) * 32 + l) * 16);
#pragma unroll
        for (int q = 0; q < 4; q++) { *(uint4*)(xfA + 4 * q) = pA[q]; *(uint4*)(xfB + 4 * q) = pB[q]; }
    }
    const float cxnA0 = g_cxn[ig + (l >> 2)];
    const float cxnA1 = g_cxn[ig + (l >> 2) + 8];
    const float cxnB0 = g_cxn[ig + (l >> 2) + 16];
    const float cxnB1 = g_cxn[ig + (l >> 2) + 24];
    const float C2 = 2.f * __ldg(ls) * LOG2E;

    float o0A[4] = {0.f, 0.f, 0.f, 0.f}, o1A[4] = {0.f, 0.f, 0.f, 0.f};
    float o0B[4] = {0.f, 0.f, 0.f, 0.f}, o1B[4] = {0.f, 0.f, 0.f, 0.f};

    issue_loads(smb, tstart, 0, tid);
    CP_COMMIT();

    for (int tt = 0; tt < tcnt; tt++) {
        CP_WAIT0();
        __syncthreads();
        if (tt + 1 < tcnt) { issue_loads(smb, tstart + tt + 1, (tt + 1) & 1, tid); CP_COMMIT(); }
        const int buf = tt & 1;
        const char* syb = sm + buf * 8192;
        const char* sbb = sm + 16384 + buf * 4096;
        const char* scy = sm + 24576 + buf * 256;

#pragma unroll
        for (int g = 0; g < 4; g++) {
            uint32_t wahA[4], walA[4], wahB[4], walB[4];
            const char* yb0 = syb + (g * 2) * 1024 + l * 32;
            const char* yb1 = syb + (g * 2 + 1) * 1024 + l * 32;
            uint4 y00 = *(const uint4*)yb0;
            uint4 y01 = *(const uint4*)(yb0 + 16);
            uint4 y10 = *(const uint4*)yb1;
            uint4 y11 = *(const uint4*)(yb1 + 16);

            // ---- GEMM1 burst: 24 MMAs, 4 chains (sA,sB,tA,tB) round-robin ----
            float sA[4] = {0.f, 0.f, 0.f, 0.f}, sB[4] = {0.f, 0.f, 0.f, 0.f};
            float tA[4] = {0.f, 0.f, 0.f, 0.f}, tB[4] = {0.f, 0.f, 0.f, 0.f};
            mma_bf16(sA, xfA + 0,  y00.x, y00.y);
            mma_bf16(sB, xfB + 0,  y00.x, y00.y);
            mma_bf16(tA, xfA + 0,  y10.x, y10.y);
            mma_bf16(tB, xfB + 0,  y10.x, y10.y);
            mma_bf16(sA, xfA + 4,  y00.z, y00.w);
            mma_bf16(sB, xfB + 4,  y00.z, y00.w);
            mma_bf16(tA, xfA + 4,  y10.z, y10.w);
            mma_bf16(tB, xfB + 4,  y10.z, y10.w);
            mma_bf16(sA, xfA + 0,  y01.x, y01.y);
            mma_bf16(sB, xfB + 0,  y01.x, y01.y);
            mma_bf16(tA, xfA + 0,  y11.x, y11.y);
            mma_bf16(tB, xfB + 0,  y11.x, y11.y);
            mma_bf16(sA, xfA + 4,  y01.z, y01.w);
            mma_bf16(sB, xfB + 4,  y01.z, y01.w);
            mma_bf16(tA, xfA + 4,  y11.z, y11.w);
            mma_bf16(tB, xfB + 4,  y11.z, y11.w);
            mma_bf16(sA, xfA + 8,  y00.x, y00.y);
            mma_bf16(sB, xfB + 8,  y00.x, y00.y);
            mma_bf16(tA, xfA + 8,  y10.x, y10.y);
            mma_bf16(tB, xfB + 8,  y10.x, y10.y);
            mma_bf16(sA, xfA + 12, y00.z, y00.w);
            mma_bf16(sB, xfB + 12, y00.z, y00.w);
            mma_bf16(tA, xfA + 12, y10.z, y10.w);
            mma_bf16(tB, xfB + 12, y10.z, y10.w);

            // ---- epilogue h0 ----
            {
                float2 cy = *(const float2*)(scy + (g * 2) * 32 + (l & 3) * 8);
                float w0 = ex2f(fminf(fmaf(C2, sA[0], cxnA0 + cy.x), 0.f));
                float w1 = ex2f(fminf(fmaf(C2, sA[1], cxnA0 + cy.y), 0.f));
                float w2 = ex2f(fminf(fmaf(C2, sA[2], cxnA1 + cy.x), 0.f));
                float w3 = ex2f(fminf(fmaf(C2, sA[3], cxnA1 + cy.y), 0.f));
                uint32_t h01 = pk2(w0, w1), h23 = pk2(w2, w3);
                wahA[0] = h01; wahA[1] = h23;
                walA[0] = pk2(w0 - bflo(h01), w1 - bfhi(h01));
                walA[1] = pk2(w2 - bflo(h23), w3 - bfhi(h23));
                float v0 = ex2f(fminf(fmaf(C2, sB[0], cxnB0 + cy.x), 0.f));
                float v1 = ex2f(fminf(fmaf(C2, sB[1], cxnB0 + cy.y), 0.f));
                float v2 = ex2f(fminf(fmaf(C2, sB[2], cxnB1 + cy.x), 0.f));
                float v3 = ex2f(fminf(fmaf(C2, sB[3], cxnB1 + cy.y), 0.f));
                uint32_t g01 = pk2(v0, v1), g23 = pk2(v2, v3);
                wahB[0] = g01; wahB[1] = g23;
                walB[0] = pk2(v0 - bflo(g01), v1 - bfhi(g01));
                walB[1] = pk2(v2 - bflo(g23), v3 - bfhi(g23));
            }
            // ---- epilogue h1 ----
            {
                float2 cy = *(const float2*)(scy + (g * 2 + 1) * 32 + (l & 3) * 8);
                float w0 = ex2f(fminf(fmaf(C2, tA[0], cxnA0 + cy.x), 0.f));
                float w1 = ex2f(fminf(fmaf(C2, tA[1], cxnA0 + cy.y), 0.f));
                float w2 = ex2f(fminf(fmaf(C2, tA[2], cxnA1 + cy.x), 0.f));
                float w3 = ex2f(fminf(fmaf(C2, tA[3], cxnA1 + cy.y), 0.f));
                uint32_t h01 = pk2(w0, w1), h23 = pk2(w2, w3);
                wahA[2] = h01; wahA[3] = h23;
                walA[2] = pk2(w0 - bflo(h01), w1 - bfhi(h01));
                walA[3] = pk2(w2 - bflo(h23), w3 - bfhi(h23));
                float v0 = ex2f(fminf(fmaf(C2, tB[0], cxnB0 + cy.x), 0.f));
                float v1 = ex2f(fminf(fmaf(C2, tB[1], cxnB0 + cy.y), 0.f));
                float v2 = ex2f(fminf(fmaf(C2, tB[2], cxnB1 + cy.x), 0.f));
                float v3 = ex2f(fminf(fmaf(C2, tB[3], cxnB1 + cy.y), 0.f));
                uint32_t g01 = pk2(v0, v1), g23 = pk2(v2, v3);
                wahB[2] = g01; wahB[3] = g23;
                walB[2] = pk2(v0 - bflo(g01), v1 - bfhi(g01));
                walB[3] = pk2(v2 - bflo(g23), v3 - bfhi(g23));
            }
            // ---- GEMM2: 4 accumulator chains round-robin ----
            uint4 b0 = *(const uint4*)(sbb + (g * 2) * 512 + l * 16);
            uint4 b1 = *(const uint4*)(sbb + (g * 2 + 1) * 512 + l * 16);
            mma_bf16(o0A, wahA, b0.x, b0.y);
            mma_bf16(o0B, wahB, b0.x, b0.y);
            mma_bf16(o1A, wahA, b1.x, b1.y);
            mma_bf16(o1B, wahB, b1.x, b1.y);
            mma_bf16(o0A, wahA, b0.z, b0.w);
            mma_bf16(o0B, wahB, b0.z, b0.w);
            mma_bf16(o1A, wahA, b1.z, b1.w);
            mma_bf16(o1B, wahB, b1.z, b1.w);
            mma_bf16(o0A, walA, b0.x, b0.y);
            mma_bf16(o0B, walB, b0.x, b0.y);
            mma_bf16(o1A, walA, b1.x, b1.y);
            mma_bf16(o1B, walB, b1.x, b1.y);
        }
    }

    // partial write: slice-local buffer
    float* op = g_Op + (size_t)sl * (NP * 16);
    const int cb = 2 * (l & 3);
    const int rA = ig + (l >> 2), rB = rA + 16;
    *(float2*)(op + (size_t)rA * 16 + cb)            = make_float2(o0A[0], o0A[1]);
    *(float2*)(op + (size_t)rA * 16 + 8 + cb)        = make_float2(o1A[0], o1A[1]);
    *(float2*)(op + (size_t)(rA + 8) * 16 + cb)      = make_float2(o0A[2], o0A[3]);
    *(float2*)(op + (size_t)(rA + 8) * 16 + 8 + cb)  = make_float2(o1A[2], o1A[3]);
    *(float2*)(op + (size_t)rB * 16 + cb)            = make_float2(o0B[0], o0B[1]);
    *(float2*)(op + (size_t)rB * 16 + 8 + cb)        = make_float2(o1B[0], o1B[1]);
    *(float2*)(op + (size_t)(rB + 8) * 16 + cb)      = make_float2(o0B[2], o0B[3]);
    *(float2*)(op + (size_t)(rB + 8) * 16 + 8 + cb)  = make_float2(o1B[2], o1B[3]);
}

// ================= deterministic slice reduction =================
__global__ void reduce_k(float* __restrict__ out) {
    int idx = blockIdx.x * 256 + threadIdx.x;
    float4 o = ((const float4*)g_Op)[idx];
#pragma unroll
    for (int s = 1; s < NSL; s++) {
        float4 v = ((const float4*)(g_Op + (size_t)s * NP * 16))[idx];
        o.x += v.x; o.y += v.y; o.z += v.z; o.w += v.w;   // fixed slice order
    }
    ((float4*)out)[idx] = o;
}

extern "C" void kernel_launch(void* const* d_in, const int* in_sizes, int n_in,
                              void* d_out, int out_size) {
    const float* ls = (const float*)d_in[0];
    const float* x  = (const float*)d_in[1];
    const float* y  = (const float*)d_in[2];
    const float* b  = (const float*)d_in[3];
    float* out = (float*)d_out;

    prep_all<<<1280, 128>>>(ls, x, y, b);
    rbf_main<<<dim3(128, NSL), 128>>>(ls);
    reduce_k<<<256, 256>>>(out);
}